// round 11
// baseline (speedup 1.0000x reference)
#include <cuda_runtime.h>
#include <cuda_bf16.h>
#include <math.h>

#define EMBED 1024
#define NHEAD 16
#define DK    64
#define BATCH 4
#define SEQ   2048
#define MTOK  (BATCH*SEQ)   // 8192

// -------- scratch (device globals; no allocation allowed) --------
__device__ float g_x [(size_t)MTOK*EMBED];          // x in tf32 bits
__device__ float g_wq[(size_t)EMBED*EMBED];         // weights in tf32 bits
__device__ float g_wk[(size_t)EMBED*EMBED];
__device__ float g_wv[(size_t)EMBED*EMBED];
__device__ float g_wo[(size_t)EMBED*EMBED];
__device__ float g_q[(size_t)BATCH*NHEAD*SEQ*DK];   // [b,h,s,d] tf32 bits, pre-scaled 1/8
__device__ float g_k[(size_t)BATCH*NHEAD*SEQ*DK];   // [b,h,s,d]
__device__ float g_v[(size_t)BATCH*NHEAD*DK*SEQ];   // [b,h,d,s]  (TRANSPOSED)
__device__ float g_attn[(size_t)MTOK*EMBED];        // tf32 bits

// -------- helpers --------
__device__ __forceinline__ unsigned f2tf(float f) {
    unsigned u; asm("cvt.rna.tf32.f32 %0, %1;" : "=r"(u) : "f"(f)); return u;
}
__device__ __forceinline__ float f2tff(float f) {
    return __uint_as_float(f2tf(f));
}

__device__ __forceinline__ void mma8(float* c, const unsigned* a, const unsigned* b) {
    asm volatile("mma.sync.aligned.m16n8k8.row.col.f32.tf32.tf32.f32 "
        "{%0,%1,%2,%3},{%4,%5,%6,%7},{%8,%9},{%0,%1,%2,%3};"
        : "+f"(c[0]), "+f"(c[1]), "+f"(c[2]), "+f"(c[3])
        : "r"(a[0]), "r"(a[1]), "r"(a[2]), "r"(a[3]), "r"(b[0]), "r"(b[1]));
}

__device__ __forceinline__ void ldsm4(unsigned& r0, unsigned& r1, unsigned& r2, unsigned& r3,
                                      const unsigned* p) {
    unsigned a = (unsigned)__cvta_generic_to_shared(p);
    asm volatile("ldmatrix.sync.aligned.m8n8.x4.shared.b16 {%0,%1,%2,%3},[%4];"
        : "=r"(r0), "=r"(r1), "=r"(r2), "=r"(r3) : "r"(a));
}

__device__ __forceinline__ void cpa16(unsigned* dst, const void* src) {
    unsigned d = (unsigned)__cvta_generic_to_shared(dst);
    asm volatile("cp.async.ca.shared.global [%0], [%1], 16;" :: "r"(d), "l"(src));
}
#define CP_COMMIT() asm volatile("cp.async.commit_group;")
#define CP_WAIT(N)  asm volatile("cp.async.wait_group %0;" :: "n"(N))

// 128B-row swizzles: full 8-group XOR -> conflict-free STS/LDGSTS.128 and LDSM
__device__ __forceinline__ int sw32(int m, int k) {   // rows of 32 floats
    return m*32 + (((((k) >> 2) ^ (m & 7)) << 2) | (k & 3));
}
__device__ __forceinline__ int sw64(int r, int c) {   // rows of 64 floats
    return r*64 + (((((c) >> 2) ^ (r & 7)) << 2) | (c & 3));
}

#define BK     32
#define TBUF   (128*BK)
#define STG    (2*TBUF)
#define NSTAGE 3
#define GEMM_SMEM_BYTES (NSTAGE * STG * (int)sizeof(unsigned))   // 96KB

// ============ kernel 0: tf32 pre-conversion ============
__global__ __launch_bounds__(256) void prep_kernel(const float* __restrict__ src,
                                                   float* __restrict__ dst, int n4)
{
    int i = blockIdx.x * blockDim.x + threadIdx.x;
    if (i < n4) {
        float4 v = ((const float4*)src)[i];
        v.x = f2tff(v.x); v.y = f2tff(v.y); v.z = f2tff(v.z); v.w = f2tff(v.w);
        ((float4*)dst)[i] = v;
    }
}

// weights prep: grid.z selects which weight (all EMBED*EMBED)
__global__ __launch_bounds__(256) void prep_w_kernel(
    const float* __restrict__ w0, const float* __restrict__ w1,
    const float* __restrict__ w2, const float* __restrict__ w3,
    float* __restrict__ d0, float* __restrict__ d1,
    float* __restrict__ d2, float* __restrict__ d3)
{
    int z = blockIdx.z;
    const float* src = (z == 0) ? w0 : (z == 1 ? w1 : (z == 2 ? w2 : w3));
    float* dst       = (z == 0) ? d0 : (z == 1 ? d1 : (z == 2 ? d2 : d3));
    int i = blockIdx.x * blockDim.x + threadIdx.x;
    float4 v = ((const float4*)src)[i];
    v.x = f2tff(v.x); v.y = f2tff(v.y); v.z = f2tff(v.z); v.w = f2tff(v.w);
    ((float4*)dst)[i] = v;
}

// ============ 128x128 NT GEMM core, cp.async 3-stage pipeline ============
__device__ __forceinline__ void gemm_core(
    const float* __restrict__ A, const float* __restrict__ W,
    int row0, int col0, unsigned* smem, float acc[2][8][4])
{
    const int K = EMBED;
    int tid  = threadIdx.x;
    int lane = tid & 31, wid = tid >> 5;
    int wm = wid >> 1, wn = wid & 1;

    #pragma unroll
    for (int mt = 0; mt < 2; mt++)
        #pragma unroll
        for (int nt = 0; nt < 8; nt++)
            #pragma unroll
            for (int i = 0; i < 4; i++) acc[mt][nt][i] = 0.f;

    int fr[4], fc[4];
    #pragma unroll
    for (int i = 0; i < 4; i++) { int f = tid + 256*i; fr[i] = f >> 3; fc[i] = (f & 7) * 4; }

    int offA[2][4], offB[4][4];
    {
        int eA = (lane & 16) ? 4 : 0;
        int eB = (lane & 8)  ? 4 : 0;
        #pragma unroll
        for (int mt = 0; mt < 2; mt++) {
            int r = wm*32 + mt*16 + (lane & 15);
            #pragma unroll
            for (int s = 0; s < 4; s++) offA[mt][s] = sw32(r, s*8 + eA);
        }
        #pragma unroll
        for (int p = 0; p < 4; p++) {
            int r = wn*64 + p*16 + (lane & 7) + ((lane >> 4) & 1) * 8;
            #pragma unroll
            for (int s = 0; s < 4; s++) offB[p][s] = sw32(r, s*8 + eB);
        }
    }

    const float* Abase = A + (size_t)row0 * K;
    const float* Bbase = W + (size_t)col0 * K;

    auto issue = [&](int kt) {
        unsigned* st = smem + (kt % NSTAGE) * STG;
        const float* Ab = Abase + kt * BK;
        const float* Bb = Bbase + kt * BK;
        #pragma unroll
        for (int i = 0; i < 4; i++)
            cpa16(st + sw32(fr[i], fc[i]), Ab + (size_t)fr[i] * K + fc[i]);
        #pragma unroll
        for (int i = 0; i < 4; i++)
            cpa16(st + TBUF + sw32(fr[i], fc[i]), Bb + (size_t)fr[i] * K + fc[i]);
        CP_COMMIT();
    };

    const int NK = K / BK;   // 32
    issue(0); issue(1);
    for (int kt = 0; kt < NK; kt++) {
        if (kt + 1 < NK) { CP_WAIT(1); } else { CP_WAIT(0); }
        __syncthreads();
        if (kt + 2 < NK) issue(kt + 2);
        const unsigned* Ab = smem + (kt % NSTAGE) * STG;
        const unsigned* Bb = Ab + TBUF;
        #pragma unroll
        for (int s = 0; s < 4; s++) {
            unsigned a[2][4], b[8][2];
            #pragma unroll
            for (int mt = 0; mt < 2; mt++)
                ldsm4(a[mt][0], a[mt][1], a[mt][2], a[mt][3], Ab + offA[mt][s]);
            #pragma unroll
            for (int p = 0; p < 4; p++)
                ldsm4(b[2*p][0], b[2*p][1], b[2*p+1][0], b[2*p+1][1], Bb + offB[p][s]);
            #pragma unroll
            for (int mt = 0; mt < 2; mt++)
                #pragma unroll
                for (int nt = 0; nt < 8; nt++)
                    mma8(acc[mt][nt], a[mt], b[nt]);
        }
    }
}

// ============ Kernel 1: fused QKV projections (grid.z picks Q/K/V) ============
// V is written TRANSPOSED into g_v[b,h,d,s].
__global__ __launch_bounds__(256, 2) void qkv_kernel()
{
    extern __shared__ __align__(16) unsigned smem[];
    int row0 = blockIdx.y * 128, col0 = blockIdx.x * 128;
    int z = blockIdx.z;
    const float* W = (z == 0) ? g_wq : (z == 1 ? g_wk : g_wv);
    float scale    = (z == 0) ? 0.125f : 1.0f;

    float acc[2][8][4];
    gemm_core(g_x, W, row0, col0, smem, acc);

    int lane = threadIdx.x & 31, wid = threadIdx.x >> 5;
    int g = lane >> 2, tg = lane & 3, wm = wid >> 1, wn = wid & 1;
    #pragma unroll
    for (int mt = 0; mt < 2; mt++) {
        int r = row0 + wm*32 + mt*16 + g;
        int bb = r >> 11, ss = r & 2047;
        #pragma unroll
        for (int nt = 0; nt < 8; nt++) {
            int c = col0 + wn*64 + nt*8 + 2*tg;
            int h = c >> 6, d = c & 63;
            if (z == 2) {
                float* pv = g_v + (((size_t)(bb*NHEAD + h) * DK + d) * SEQ + ss);
                pv[0]       = f2tff(acc[mt][nt][0]);
                pv[SEQ]     = f2tff(acc[mt][nt][1]);
                pv[8]       = f2tff(acc[mt][nt][2]);
                pv[SEQ + 8] = f2tff(acc[mt][nt][3]);
            } else {
                float* dst = (z == 0) ? g_q : g_k;
                float* p0 = dst + (((size_t)(bb*NHEAD + h) * SEQ + ss) * DK + d);
                float* p1 = p0 + 8*DK;
                p0[0] = f2tff(acc[mt][nt][0] * scale); p0[1] = f2tff(acc[mt][nt][1] * scale);
                p1[0] = f2tff(acc[mt][nt][2] * scale); p1[1] = f2tff(acc[mt][nt][3] * scale);
            }
        }
    }
}

// ============ Kernel 2: flash attention, 128-query blocks ============
// 128q x 64k tiles, 256 threads = 8 warps, each warp owns 16 q-rows.
// Halves K/V L2 traffic + fill/barrier events vs 64q blocks.
// smem: [Qs 32KB][Ps 32KB][K0 16][V0 16][K1 16][V1 16] = 128KB
#define ATTN_SMEM_BYTES ((8192 + 8192 + 16384) * (int)sizeof(unsigned))
__global__ __launch_bounds__(256, 1) void attn_kernel()
{
    extern __shared__ __align__(16) unsigned asm_[];
    unsigned* Qs = asm_;             // 128 x 64
    unsigned* Ps = asm_ + 8192;      // 128 x 64
    unsigned* KV = asm_ + 16384;     // stage s: K at s*8192, Vt at s*8192+4096

    int qt = blockIdx.x, bh = blockIdx.y;
    const float* Qp = g_q + (size_t)bh * SEQ * DK + (size_t)qt * 128 * DK;
    const float* Kp = g_k + (size_t)bh * SEQ * DK;
    const float* Vp = g_v + (size_t)bh * DK * SEQ;   // [d, s]

    int tid = threadIdx.x, lane = tid & 31, wid = tid >> 5;   // wid 0..7
    int g = lane >> 2, tg = lane & 3;
    int r0 = wid*16 + g;             // first q-row (second is r0+8), 0..127

    int eA = (lane & 16) ? 4 : 0;
    int rA = wid*16 + (lane & 15);
    int eB = (lane & 8)  ? 4 : 0;
    int rB[4];
    #pragma unroll
    for (int p = 0; p < 4; p++) rB[p] = p*16 + (lane & 7) + ((lane >> 4) & 1) * 8;

    // K/V fill addresses (64-row tiles, 256 threads -> 4 float4 each)
    int adKV[4], goffK[4], goffV[4];
    #pragma unroll
    for (int i = 0; i < 4; i++) {
        int f = tid + 256*i;
        int r = f >> 4, c4 = f & 15;
        adKV[i]  = r*64 + ((c4 ^ (r & 7)) << 2);
        goffK[i] = r*64 + c4*4;
        goffV[i] = r*SEQ + c4*4;
    }

    // Q fill (128 rows, 8 float4 per thread)
    #pragma unroll
    for (int i = 0; i < 8; i++) {
        int f = tid + 256*i;
        int r = f >> 4, c4 = f & 15;
        cpa16(Qs + r*64 + ((c4 ^ (r & 7)) << 2), Qp + r*64 + c4*4);
    }
    CP_COMMIT();
    // first K/Vt tile
    #pragma unroll
    for (int i = 0; i < 4; i++) {
        cpa16(KV + adKV[i],        Kp + goffK[i]);
        cpa16(KV + 4096 + adKV[i], Vp + goffV[i]);
    }
    CP_COMMIT();

    // hoist Q fragments (reused for all 32 key tiles)
    unsigned aq[8][4];
    CP_WAIT(1);
    __syncthreads();
    #pragma unroll
    for (int kk8 = 0; kk8 < 8; kk8++)
        ldsm4(aq[kk8][0], aq[kk8][1], aq[kk8][2], aq[kk8][3], Qs + sw64(rA, kk8*8 + eA));

    float o[8][4];
    #pragma unroll
    for (int nt = 0; nt < 8; nt++)
        #pragma unroll
        for (int i = 0; i < 4; i++) o[nt][i] = 0.f;
    float m0 = -1e30f, m1 = -1e30f, l0 = 0.f, l1 = 0.f;

    const int NT = SEQ/64;
    for (int kt = 0; kt < NT; kt++) {
        CP_WAIT(0);
        __syncthreads();

        if (kt + 1 < NT) {
            unsigned* st = KV + ((kt + 1) & 1) * 8192;
            int t = (kt + 1) * 64;
            #pragma unroll
            for (int i = 0; i < 4; i++) {
                cpa16(st + adKV[i],        Kp + (size_t)t * DK + goffK[i]);
                cpa16(st + 4096 + adKV[i], Vp + t + goffV[i]);
            }
            CP_COMMIT();
        }

        const unsigned* Ks  = KV + (kt & 1) * 8192;
        const unsigned* Vts = Ks + 4096;

        // S = Q * K^T
        float s[8][4];
        #pragma unroll
        for (int nt = 0; nt < 8; nt++)
            #pragma unroll
            for (int i = 0; i < 4; i++) s[nt][i] = 0.f;
        #pragma unroll
        for (int kk8 = 0; kk8 < 8; kk8++) {
            unsigned b[8][2];
            #pragma unroll
            for (int p = 0; p < 4; p++)
                ldsm4(b[2*p][0], b[2*p][1], b[2*p+1][0], b[2*p+1][1],
                      Ks + sw64(rB[p], kk8*8 + eB));
            #pragma unroll
            for (int nt = 0; nt < 8; nt++) mma8(s[nt], aq[kk8], b[nt]);
        }

        // online softmax
        float ml0 = -1e30f, ml1 = -1e30f;
        #pragma unroll
        for (int nt = 0; nt < 8; nt++) {
            ml0 = fmaxf(ml0, fmaxf(s[nt][0], s[nt][1]));
            ml1 = fmaxf(ml1, fmaxf(s[nt][2], s[nt][3]));
        }
        ml0 = fmaxf(ml0, __shfl_xor_sync(0xffffffffu, ml0, 1));
        ml0 = fmaxf(ml0, __shfl_xor_sync(0xffffffffu, ml0, 2));
        ml1 = fmaxf(ml1, __shfl_xor_sync(0xffffffffu, ml1, 1));
        ml1 = fmaxf(ml1, __shfl_xor_sync(0xffffffffu, ml1, 2));
        float mn0 = fmaxf(m0, ml0), mn1 = fmaxf(m1, ml1);
        float al0 = __expf(m0 - mn0), al1 = __expf(m1 - mn1);
        m0 = mn0; m1 = mn1;
        float sum0 = 0.f, sum1 = 0.f;
        #pragma unroll
        for (int nt = 0; nt < 8; nt++) {
            s[nt][0] = __expf(s[nt][0] - mn0); sum0 += s[nt][0];
            s[nt][1] = __expf(s[nt][1] - mn0); sum0 += s[nt][1];
            s[nt][2] = __expf(s[nt][2] - mn1); sum1 += s[nt][2];
            s[nt][3] = __expf(s[nt][3] - mn1); sum1 += s[nt][3];
        }
        sum0 += __shfl_xor_sync(0xffffffffu, sum0, 1);
        sum0 += __shfl_xor_sync(0xffffffffu, sum0, 2);
        sum1 += __shfl_xor_sync(0xffffffffu, sum1, 1);
        sum1 += __shfl_xor_sync(0xffffffffu, sum1, 2);
        l0 = l0 * al0 + sum0;
        l1 = l1 * al1 + sum1;
        #pragma unroll
        for (int nt = 0; nt < 8; nt++) {
            o[nt][0] *= al0; o[nt][1] *= al0;
            o[nt][2] *= al1; o[nt][3] *= al1;
        }

        // P stripe -> Ps (warp-private rows)
        #pragma unroll
        for (int nt = 0; nt < 8; nt++) {
            int c = nt*8 + 2*tg;
            Ps[sw64(r0,     c)]     = f2tf(s[nt][0]);
            Ps[sw64(r0,     c + 1)] = f2tf(s[nt][1]);
            Ps[sw64(r0 + 8, c)]     = f2tf(s[nt][2]);
            Ps[sw64(r0 + 8, c + 1)] = f2tf(s[nt][3]);
        }
        __syncwarp();

        // O += P * V   (B fragment from Vt via ldmatrix, same sites as K)
        #pragma unroll
        for (int kk8 = 0; kk8 < 8; kk8++) {
            unsigned a[4], b[8][2];
            ldsm4(a[0], a[1], a[2], a[3], Ps + sw64(rA, kk8*8 + eA));
            #pragma unroll
            for (int p = 0; p < 4; p++)
                ldsm4(b[2*p][0], b[2*p][1], b[2*p+1][0], b[2*p+1][1],
                      Vts + sw64(rB[p], kk8*8 + eB));
            #pragma unroll
            for (int nt = 0; nt < 8; nt++) mma8(o[nt], a, b[nt]);
        }
    }

    // epilogue
    float inv0 = 1.f / l0, inv1 = 1.f / l1;
    int bb = bh >> 4, h = bh & 15;
    int q0 = qt*128 + r0;
    float* base0 = g_attn + ((size_t)(bb*SEQ + q0) * EMBED) + h*64;
    float* base1 = base0 + (size_t)8 * EMBED;
    #pragma unroll
    for (int nt = 0; nt < 8; nt++) {
        int d = nt*8 + 2*tg;
        base0[d]     = f2tff(o[nt][0] * inv0);
        base0[d + 1] = f2tff(o[nt][1] * inv0);
        base1[d]     = f2tff(o[nt][2] * inv1);
        base1[d + 1] = f2tff(o[nt][3] * inv1);
    }
}

// ============ Kernel 3: output projection ============
__global__ __launch_bounds__(256, 2) void oproj_kernel(float* __restrict__ out)
{
    extern __shared__ __align__(16) unsigned smem[];
    int row0 = blockIdx.y * 128, col0 = blockIdx.x * 128;
    float acc[2][8][4];
    gemm_core(g_attn, g_wo, row0, col0, smem, acc);

    int lane = threadIdx.x & 31, wid = threadIdx.x >> 5;
    int g = lane >> 2, tg = lane & 3, wm = wid >> 1, wn = wid & 1;
    #pragma unroll
    for (int mt = 0; mt < 2; mt++) {
        int r = row0 + wm*32 + mt*16 + g;
        #pragma unroll
        for (int nt = 0; nt < 8; nt++) {
            int c = col0 + wn*64 + nt*8 + 2*tg;
            float* p0 = out + (size_t)r * EMBED + c;
            float* p1 = out + (size_t)(r + 8) * EMBED + c;
            p0[0] = acc[mt][nt][0]; p0[1] = acc[mt][nt][1];
            p1[0] = acc[mt][nt][2]; p1[1] = acc[mt][nt][3];
        }
    }
}

// ============ launch ============
extern "C" void kernel_launch(void* const* d_in, const int* in_sizes, int n_in,
                              void* d_out, int out_size)
{
    const float* x  = (const float*)d_in[0];
    const float* Wq = (const float*)d_in[1];
    const float* Wk = (const float*)d_in[2];
    const float* Wv = (const float*)d_in[3];
    const float* Wo = (const float*)d_in[4];
    float* out = (float*)d_out;

    cudaFuncSetAttribute(qkv_kernel,   cudaFuncAttributeMaxDynamicSharedMemorySize, GEMM_SMEM_BYTES);
    cudaFuncSetAttribute(oproj_kernel, cudaFuncAttributeMaxDynamicSharedMemorySize, GEMM_SMEM_BYTES);
    cudaFuncSetAttribute(attn_kernel,  cudaFuncAttributeMaxDynamicSharedMemorySize, ATTN_SMEM_BYTES);

    float* p_x;  cudaGetSymbolAddress((void**)&p_x,  g_x);
    float* p_wq; cudaGetSymbolAddress((void**)&p_wq, g_wq);
    float* p_wk; cudaGetSymbolAddress((void**)&p_wk, g_wk);
    float* p_wv; cudaGetSymbolAddress((void**)&p_wv, g_wv);
    float* p_wo; cudaGetSymbolAddress((void**)&p_wo, g_wo);

    int nx4 = MTOK*EMBED/4, nw4 = EMBED*EMBED/4;
    prep_kernel<<<(nx4 + 255)/256, 256>>>(x, p_x, nx4);
    prep_w_kernel<<<dim3(nw4/256, 1, 4), 256>>>(Wq, Wk, Wv, Wo, p_wq, p_wk, p_wv, p_wo);

    qkv_kernel<<<dim3(EMBED/128, MTOK/128, 3), 256, GEMM_SMEM_BYTES>>>();
    attn_kernel<<<dim3(SEQ/128, BATCH*NHEAD), 256, ATTN_SMEM_BYTES>>>();
    oproj_kernel<<<dim3(EMBED/128, MTOK/128), 256, GEMM_SMEM_BYTES>>>(out);
}

// round 12
// speedup vs baseline: 1.0283x; 1.0283x over previous
#include <cuda_runtime.h>
#include <cuda_bf16.h>
#include <math.h>

#define EMBED 1024
#define NHEAD 16
#define DK    64
#define BATCH 4
#define SEQ   2048
#define MTOK  (BATCH*SEQ)   // 8192

// -------- scratch (device globals; no allocation allowed) --------
__device__ float g_x [(size_t)MTOK*EMBED];          // x in tf32 bits
__device__ float g_wq[(size_t)EMBED*EMBED];         // weights in tf32 bits
__device__ float g_wk[(size_t)EMBED*EMBED];
__device__ float g_wv[(size_t)EMBED*EMBED];
__device__ float g_wo[(size_t)EMBED*EMBED];
__device__ float g_q[(size_t)BATCH*NHEAD*SEQ*DK];   // [b,h,s,d] tf32 bits, pre-scaled 1/8
__device__ float g_k[(size_t)BATCH*NHEAD*SEQ*DK];   // [b,h,s,d]
__device__ float g_v[(size_t)BATCH*NHEAD*DK*SEQ];   // [b,h,d,s]  (TRANSPOSED)
__device__ float g_attn[(size_t)MTOK*EMBED];        // tf32 bits

// -------- helpers --------
__device__ __forceinline__ unsigned f2tf(float f) {
    unsigned u; asm("cvt.rna.tf32.f32 %0, %1;" : "=r"(u) : "f"(f)); return u;
}
__device__ __forceinline__ float f2tff(float f) {
    return __uint_as_float(f2tf(f));
}

__device__ __forceinline__ void mma8(float* c, const unsigned* a, const unsigned* b) {
    asm volatile("mma.sync.aligned.m16n8k8.row.col.f32.tf32.tf32.f32 "
        "{%0,%1,%2,%3},{%4,%5,%6,%7},{%8,%9},{%0,%1,%2,%3};"
        : "+f"(c[0]), "+f"(c[1]), "+f"(c[2]), "+f"(c[3])
        : "r"(a[0]), "r"(a[1]), "r"(a[2]), "r"(a[3]), "r"(b[0]), "r"(b[1]));
}

__device__ __forceinline__ void ldsm4(unsigned& r0, unsigned& r1, unsigned& r2, unsigned& r3,
                                      const unsigned* p) {
    unsigned a = (unsigned)__cvta_generic_to_shared(p);
    asm volatile("ldmatrix.sync.aligned.m8n8.x4.shared.b16 {%0,%1,%2,%3},[%4];"
        : "=r"(r0), "=r"(r1), "=r"(r2), "=r"(r3) : "r"(a));
}

__device__ __forceinline__ void cpa16(unsigned* dst, const void* src) {
    unsigned d = (unsigned)__cvta_generic_to_shared(dst);
    asm volatile("cp.async.ca.shared.global [%0], [%1], 16;" :: "r"(d), "l"(src));
}
#define CP_COMMIT() asm volatile("cp.async.commit_group;")
#define CP_WAIT(N)  asm volatile("cp.async.wait_group %0;" :: "n"(N))

// 128B-row swizzles: full 8-group XOR -> conflict-free STS/LDGSTS.128 and LDSM
__device__ __forceinline__ int sw32(int m, int k) {   // rows of 32 floats
    return m*32 + (((((k) >> 2) ^ (m & 7)) << 2) | (k & 3));
}
__device__ __forceinline__ int sw64(int r, int c) {   // rows of 64 floats
    return r*64 + (((((c) >> 2) ^ (r & 7)) << 2) | (c & 3));
}

#define BK     32
#define TBUF   (128*BK)
#define STG    (2*TBUF)
#define NSTAGE 3
#define GEMM_SMEM_BYTES (NSTAGE * STG * (int)sizeof(unsigned))   // 96KB

// ============ kernel 0: tf32 pre-conversion ============
__global__ __launch_bounds__(256) void prep_kernel(const float* __restrict__ src,
                                                   float* __restrict__ dst, int n4)
{
    int i = blockIdx.x * blockDim.x + threadIdx.x;
    if (i < n4) {
        float4 v = ((const float4*)src)[i];
        v.x = f2tff(v.x); v.y = f2tff(v.y); v.z = f2tff(v.z); v.w = f2tff(v.w);
        ((float4*)dst)[i] = v;
    }
}

__global__ __launch_bounds__(256) void prep_w_kernel(
    const float* __restrict__ w0, const float* __restrict__ w1,
    const float* __restrict__ w2, const float* __restrict__ w3,
    float* __restrict__ d0, float* __restrict__ d1,
    float* __restrict__ d2, float* __restrict__ d3)
{
    int z = blockIdx.z;
    const float* src = (z == 0) ? w0 : (z == 1 ? w1 : (z == 2 ? w2 : w3));
    float* dst       = (z == 0) ? d0 : (z == 1 ? d1 : (z == 2 ? d2 : d3));
    int i = blockIdx.x * blockDim.x + threadIdx.x;
    float4 v = ((const float4*)src)[i];
    v.x = f2tff(v.x); v.y = f2tff(v.y); v.z = f2tff(v.z); v.w = f2tff(v.w);
    ((float4*)dst)[i] = v;
}

// ============ 128x128 NT GEMM core, cp.async 3-stage pipeline ============
// 128 threads = 4 warps in 2(m) x 2(n); warp tile 64x64 = 4 mtiles x 8 ntiles.
// 8 ldsm4 per 32 mma (vs 6 per 16 before) -> 33% fewer LDS wavefronts per FLOP.
__device__ __forceinline__ void gemm_core(
    const float* __restrict__ A, const float* __restrict__ W,
    int row0, int col0, unsigned* smem, float acc[4][8][4])
{
    const int K = EMBED;
    int tid  = threadIdx.x;
    int lane = tid & 31, wid = tid >> 5;
    int wm = wid >> 1, wn = wid & 1;

    #pragma unroll
    for (int mt = 0; mt < 4; mt++)
        #pragma unroll
        for (int nt = 0; nt < 8; nt++)
            #pragma unroll
            for (int i = 0; i < 4; i++) acc[mt][nt][i] = 0.f;

    int fr[8], fc[8];
    #pragma unroll
    for (int i = 0; i < 8; i++) { int f = tid + 128*i; fr[i] = f >> 3; fc[i] = (f & 7) * 4; }

    int offA[4][4], offB[4][4];
    {
        int eA = (lane & 16) ? 4 : 0;
        int eB = (lane & 8)  ? 4 : 0;
        #pragma unroll
        for (int mt = 0; mt < 4; mt++) {
            int r = wm*64 + mt*16 + (lane & 15);
            #pragma unroll
            for (int s = 0; s < 4; s++) offA[mt][s] = sw32(r, s*8 + eA);
        }
        #pragma unroll
        for (int p = 0; p < 4; p++) {
            int r = wn*64 + p*16 + (lane & 7) + ((lane >> 4) & 1) * 8;
            #pragma unroll
            for (int s = 0; s < 4; s++) offB[p][s] = sw32(r, s*8 + eB);
        }
    }

    const float* Abase = A + (size_t)row0 * K;
    const float* Bbase = W + (size_t)col0 * K;

    auto issue = [&](int kt) {
        unsigned* st = smem + (kt % NSTAGE) * STG;
        const float* Ab = Abase + kt * BK;
        const float* Bb = Bbase + kt * BK;
        #pragma unroll
        for (int i = 0; i < 8; i++)
            cpa16(st + sw32(fr[i], fc[i]), Ab + (size_t)fr[i] * K + fc[i]);
        #pragma unroll
        for (int i = 0; i < 8; i++)
            cpa16(st + TBUF + sw32(fr[i], fc[i]), Bb + (size_t)fr[i] * K + fc[i]);
        CP_COMMIT();
    };

    const int NK = K / BK;   // 32
    issue(0); issue(1);
    for (int kt = 0; kt < NK; kt++) {
        if (kt + 1 < NK) { CP_WAIT(1); } else { CP_WAIT(0); }
        __syncthreads();
        if (kt + 2 < NK) issue(kt + 2);
        const unsigned* Ab = smem + (kt % NSTAGE) * STG;
        const unsigned* Bb = Ab + TBUF;
        #pragma unroll
        for (int s = 0; s < 4; s++) {
            unsigned a[4][4], b[8][2];
            #pragma unroll
            for (int mt = 0; mt < 4; mt++)
                ldsm4(a[mt][0], a[mt][1], a[mt][2], a[mt][3], Ab + offA[mt][s]);
            #pragma unroll
            for (int p = 0; p < 4; p++)
                ldsm4(b[2*p][0], b[2*p][1], b[2*p+1][0], b[2*p+1][1], Bb + offB[p][s]);
            #pragma unroll
            for (int mt = 0; mt < 4; mt++)
                #pragma unroll
                for (int nt = 0; nt < 8; nt++)
                    mma8(acc[mt][nt], a[mt], b[nt]);
        }
    }
}

// ============ Kernel 1: fused QKV projections (grid.z picks Q/K/V) ============
// V is written TRANSPOSED into g_v[b,h,d,s].
__global__ __launch_bounds__(128, 2) void qkv_kernel()
{
    extern __shared__ __align__(16) unsigned smem[];
    int row0 = blockIdx.y * 128, col0 = blockIdx.x * 128;
    int z = blockIdx.z;
    const float* W = (z == 0) ? g_wq : (z == 1 ? g_wk : g_wv);
    float scale    = (z == 0) ? 0.125f : 1.0f;

    float acc[4][8][4];
    gemm_core(g_x, W, row0, col0, smem, acc);

    int lane = threadIdx.x & 31, wid = threadIdx.x >> 5;
    int g = lane >> 2, tg = lane & 3, wm = wid >> 1, wn = wid & 1;
    #pragma unroll
    for (int mt = 0; mt < 4; mt++) {
        int r = row0 + wm*64 + mt*16 + g;
        int bb = r >> 11, ss = r & 2047;
        #pragma unroll
        for (int nt = 0; nt < 8; nt++) {
            int c = col0 + wn*64 + nt*8 + 2*tg;
            int h = c >> 6, d = c & 63;
            if (z == 2) {
                float* pv = g_v + (((size_t)(bb*NHEAD + h) * DK + d) * SEQ + ss);
                pv[0]       = f2tff(acc[mt][nt][0]);
                pv[SEQ]     = f2tff(acc[mt][nt][1]);
                pv[8]       = f2tff(acc[mt][nt][2]);
                pv[SEQ + 8] = f2tff(acc[mt][nt][3]);
            } else {
                float* dst = (z == 0) ? g_q : g_k;
                float* p0 = dst + (((size_t)(bb*NHEAD + h) * SEQ + ss) * DK + d);
                float* p1 = p0 + 8*DK;
                p0[0] = f2tff(acc[mt][nt][0] * scale); p0[1] = f2tff(acc[mt][nt][1] * scale);
                p1[0] = f2tff(acc[mt][nt][2] * scale); p1[1] = f2tff(acc[mt][nt][3] * scale);
            }
        }
    }
}

// ============ Kernel 2: flash attention (R6 config: 64q, 128 threads, 2 CTA/SM) ============
#define ATTN_SMEM_BYTES (6 * 64 * 64 * (int)sizeof(unsigned))   // 96KB
__global__ __launch_bounds__(128, 2) void attn_kernel()
{
    extern __shared__ __align__(16) unsigned asm_[];
    unsigned* Qs = asm_;
    unsigned* Ps = asm_ + 4096;
    unsigned* KV = asm_ + 8192;   // stage s: K at s*8192, Vt at s*8192+4096

    int qt = blockIdx.x, bh = blockIdx.y;
    const float* Qp = g_q + (size_t)bh * SEQ * DK + (size_t)qt * 64 * DK;
    const float* Kp = g_k + (size_t)bh * SEQ * DK;
    const float* Vp = g_v + (size_t)bh * DK * SEQ;   // [d, s]

    int tid = threadIdx.x, lane = tid & 31, wid = tid >> 5;
    int g = lane >> 2, tg = lane & 3;
    int r0 = wid*16 + g;

    int eA = (lane & 16) ? 4 : 0;
    int rA = wid*16 + (lane & 15);
    int eB = (lane & 8)  ? 4 : 0;
    int rB[4];
    #pragma unroll
    for (int p = 0; p < 4; p++) rB[p] = p*16 + (lane & 7) + ((lane >> 4) & 1) * 8;

    int adS[8], goff[8], goffV[8];
    #pragma unroll
    for (int i = 0; i < 8; i++) {
        int f = tid + 128*i;
        int r = f >> 4, c4 = f & 15;
        adS[i]   = r*64 + ((c4 ^ (r & 7)) << 2);
        goff[i]  = r*64 + c4*4;
        goffV[i] = r*SEQ + c4*4;
    }

    #pragma unroll
    for (int i = 0; i < 8; i++) cpa16(Qs + adS[i], Qp + goff[i]);
    CP_COMMIT();
    #pragma unroll
    for (int i = 0; i < 8; i++) {
        cpa16(KV + adS[i],        Kp + goff[i]);
        cpa16(KV + 4096 + adS[i], Vp + goffV[i]);
    }
    CP_COMMIT();

    unsigned aq[8][4];
    CP_WAIT(1);
    __syncthreads();
    #pragma unroll
    for (int kk8 = 0; kk8 < 8; kk8++)
        ldsm4(aq[kk8][0], aq[kk8][1], aq[kk8][2], aq[kk8][3], Qs + sw64(rA, kk8*8 + eA));

    float o[8][4];
    #pragma unroll
    for (int nt = 0; nt < 8; nt++)
        #pragma unroll
        for (int i = 0; i < 4; i++) o[nt][i] = 0.f;
    float m0 = -1e30f, m1 = -1e30f, l0 = 0.f, l1 = 0.f;

    const int NT = SEQ/64;
    for (int kt = 0; kt < NT; kt++) {
        CP_WAIT(0);
        __syncthreads();

        if (kt + 1 < NT) {
            unsigned* st = KV + ((kt + 1) & 1) * 8192;
            int t  = (kt + 1) * 64;
            #pragma unroll
            for (int i = 0; i < 8; i++) {
                cpa16(st + adS[i],        Kp + (size_t)t * DK + goff[i]);
                cpa16(st + 4096 + adS[i], Vp + t + goffV[i]);
            }
            CP_COMMIT();
        }

        const unsigned* Ks  = KV + (kt & 1) * 8192;
        const unsigned* Vts = Ks + 4096;

        float s[8][4];
        #pragma unroll
        for (int nt = 0; nt < 8; nt++)
            #pragma unroll
            for (int i = 0; i < 4; i++) s[nt][i] = 0.f;
        #pragma unroll
        for (int kk8 = 0; kk8 < 8; kk8++) {
            unsigned b[8][2];
            #pragma unroll
            for (int p = 0; p < 4; p++)
                ldsm4(b[2*p][0], b[2*p][1], b[2*p+1][0], b[2*p+1][1],
                      Ks + sw64(rB[p], kk8*8 + eB));
            #pragma unroll
            for (int nt = 0; nt < 8; nt++) mma8(s[nt], aq[kk8], b[nt]);
        }

        float ml0 = -1e30f, ml1 = -1e30f;
        #pragma unroll
        for (int nt = 0; nt < 8; nt++) {
            ml0 = fmaxf(ml0, fmaxf(s[nt][0], s[nt][1]));
            ml1 = fmaxf(ml1, fmaxf(s[nt][2], s[nt][3]));
        }
        ml0 = fmaxf(ml0, __shfl_xor_sync(0xffffffffu, ml0, 1));
        ml0 = fmaxf(ml0, __shfl_xor_sync(0xffffffffu, ml0, 2));
        ml1 = fmaxf(ml1, __shfl_xor_sync(0xffffffffu, ml1, 1));
        ml1 = fmaxf(ml1, __shfl_xor_sync(0xffffffffu, ml1, 2));
        float mn0 = fmaxf(m0, ml0), mn1 = fmaxf(m1, ml1);
        float al0 = __expf(m0 - mn0), al1 = __expf(m1 - mn1);
        m0 = mn0; m1 = mn1;
        float sum0 = 0.f, sum1 = 0.f;
        #pragma unroll
        for (int nt = 0; nt < 8; nt++) {
            s[nt][0] = __expf(s[nt][0] - mn0); sum0 += s[nt][0];
            s[nt][1] = __expf(s[nt][1] - mn0); sum0 += s[nt][1];
            s[nt][2] = __expf(s[nt][2] - mn1); sum1 += s[nt][2];
            s[nt][3] = __expf(s[nt][3] - mn1); sum1 += s[nt][3];
        }
        sum0 += __shfl_xor_sync(0xffffffffu, sum0, 1);
        sum0 += __shfl_xor_sync(0xffffffffu, sum0, 2);
        sum1 += __shfl_xor_sync(0xffffffffu, sum1, 1);
        sum1 += __shfl_xor_sync(0xffffffffu, sum1, 2);
        l0 = l0 * al0 + sum0;
        l1 = l1 * al1 + sum1;
        #pragma unroll
        for (int nt = 0; nt < 8; nt++) {
            o[nt][0] *= al0; o[nt][1] *= al0;
            o[nt][2] *= al1; o[nt][3] *= al1;
        }

        #pragma unroll
        for (int nt = 0; nt < 8; nt++) {
            int c = nt*8 + 2*tg;
            Ps[sw64(r0,     c)]     = f2tf(s[nt][0]);
            Ps[sw64(r0,     c + 1)] = f2tf(s[nt][1]);
            Ps[sw64(r0 + 8, c)]     = f2tf(s[nt][2]);
            Ps[sw64(r0 + 8, c + 1)] = f2tf(s[nt][3]);
        }
        __syncwarp();

        #pragma unroll
        for (int kk8 = 0; kk8 < 8; kk8++) {
            unsigned a[4], b[8][2];
            ldsm4(a[0], a[1], a[2], a[3], Ps + sw64(rA, kk8*8 + eA));
            #pragma unroll
            for (int p = 0; p < 4; p++)
                ldsm4(b[2*p][0], b[2*p][1], b[2*p+1][0], b[2*p+1][1],
                      Vts + sw64(rB[p], kk8*8 + eB));
            #pragma unroll
            for (int nt = 0; nt < 8; nt++) mma8(o[nt], a, b[nt]);
        }
    }

    float inv0 = 1.f / l0, inv1 = 1.f / l1;
    int bb = bh >> 4, h = bh & 15;
    int q0 = qt*64 + r0;
    float* base0 = g_attn + ((size_t)(bb*SEQ + q0) * EMBED) + h*64;
    float* base1 = base0 + (size_t)8 * EMBED;
    #pragma unroll
    for (int nt = 0; nt < 8; nt++) {
        int d = nt*8 + 2*tg;
        base0[d]     = f2tff(o[nt][0] * inv0);
        base0[d + 1] = f2tff(o[nt][1] * inv0);
        base1[d]     = f2tff(o[nt][2] * inv1);
        base1[d + 1] = f2tff(o[nt][3] * inv1);
    }
}

// ============ Kernel 3: output projection ============
__global__ __launch_bounds__(128, 2) void oproj_kernel(float* __restrict__ out)
{
    extern __shared__ __align__(16) unsigned smem[];
    int row0 = blockIdx.y * 128, col0 = blockIdx.x * 128;
    float acc[4][8][4];
    gemm_core(g_attn, g_wo, row0, col0, smem, acc);

    int lane = threadIdx.x & 31, wid = threadIdx.x >> 5;
    int g = lane >> 2, tg = lane & 3, wm = wid >> 1, wn = wid & 1;
    #pragma unroll
    for (int mt = 0; mt < 4; mt++) {
        int r = row0 + wm*64 + mt*16 + g;
        #pragma unroll
        for (int nt = 0; nt < 8; nt++) {
            int c = col0 + wn*64 + nt*8 + 2*tg;
            float* p0 = out + (size_t)r * EMBED + c;
            float* p1 = out + (size_t)(r + 8) * EMBED + c;
            p0[0] = acc[mt][nt][0]; p0[1] = acc[mt][nt][1];
            p1[0] = acc[mt][nt][2]; p1[1] = acc[mt][nt][3];
        }
    }
}

// ============ launch ============
extern "C" void kernel_launch(void* const* d_in, const int* in_sizes, int n_in,
                              void* d_out, int out_size)
{
    const float* x  = (const float*)d_in[0];
    const float* Wq = (const float*)d_in[1];
    const float* Wk = (const float*)d_in[2];
    const float* Wv = (const float*)d_in[3];
    const float* Wo = (const float*)d_in[4];
    float* out = (float*)d_out;

    cudaFuncSetAttribute(qkv_kernel,   cudaFuncAttributeMaxDynamicSharedMemorySize, GEMM_SMEM_BYTES);
    cudaFuncSetAttribute(oproj_kernel, cudaFuncAttributeMaxDynamicSharedMemorySize, GEMM_SMEM_BYTES);
    cudaFuncSetAttribute(attn_kernel,  cudaFuncAttributeMaxDynamicSharedMemorySize, ATTN_SMEM_BYTES);

    float* p_x;  cudaGetSymbolAddress((void**)&p_x,  g_x);
    float* p_wq; cudaGetSymbolAddress((void**)&p_wq, g_wq);
    float* p_wk; cudaGetSymbolAddress((void**)&p_wk, g_wk);
    float* p_wv; cudaGetSymbolAddress((void**)&p_wv, g_wv);
    float* p_wo; cudaGetSymbolAddress((void**)&p_wo, g_wo);

    int nx4 = MTOK*EMBED/4, nw4 = EMBED*EMBED/4;
    prep_kernel<<<(nx4 + 255)/256, 256>>>(x, p_x, nx4);
    prep_w_kernel<<<dim3(nw4/256, 1, 4), 256>>>(Wq, Wk, Wv, Wo, p_wq, p_wk, p_wv, p_wo);

    qkv_kernel<<<dim3(EMBED/128, MTOK/128, 3), 128, GEMM_SMEM_BYTES>>>();
    attn_kernel<<<dim3(SEQ/64, BATCH*NHEAD), 128, ATTN_SMEM_BYTES>>>();
    oproj_kernel<<<dim3(EMBED/128, MTOK/128), 128, GEMM_SMEM_BYTES>>>(out);
}

// round 13
// speedup vs baseline: 1.1455x; 1.1140x over previous
#include <cuda_runtime.h>
#include <cuda_bf16.h>
#include <math.h>

#define EMBED 1024
#define NHEAD 16
#define DK    64
#define BATCH 4
#define SEQ   2048
#define MTOK  (BATCH*SEQ)   // 8192

// -------- scratch (device globals; no allocation allowed) --------
__device__ float g_x [(size_t)MTOK*EMBED];          // x in tf32 bits
__device__ float g_wq[(size_t)EMBED*EMBED];         // weights in tf32 bits
__device__ float g_wk[(size_t)EMBED*EMBED];
__device__ float g_wv[(size_t)EMBED*EMBED];
__device__ float g_wo[(size_t)EMBED*EMBED];
__device__ float g_q[(size_t)BATCH*NHEAD*SEQ*DK];   // [b,h,s,d] tf32 bits, pre-scaled 1/8
__device__ float g_k[(size_t)BATCH*NHEAD*SEQ*DK];   // [b,h,s,d]
__device__ float g_v[(size_t)BATCH*NHEAD*DK*SEQ];   // [b,h,d,s]  (TRANSPOSED)
__device__ float g_attn[(size_t)MTOK*EMBED];        // tf32 bits

// -------- helpers --------
__device__ __forceinline__ unsigned f2tf(float f) {
    unsigned u; asm("cvt.rna.tf32.f32 %0, %1;" : "=r"(u) : "f"(f)); return u;
}
__device__ __forceinline__ float f2tff(float f) {
    return __uint_as_float(f2tf(f));
}

__device__ __forceinline__ void mma8(float* c, const unsigned* a, const unsigned* b) {
    asm volatile("mma.sync.aligned.m16n8k8.row.col.f32.tf32.tf32.f32 "
        "{%0,%1,%2,%3},{%4,%5,%6,%7},{%8,%9},{%0,%1,%2,%3};"
        : "+f"(c[0]), "+f"(c[1]), "+f"(c[2]), "+f"(c[3])
        : "r"(a[0]), "r"(a[1]), "r"(a[2]), "r"(a[3]), "r"(b[0]), "r"(b[1]));
}

__device__ __forceinline__ void ldsm4(unsigned& r0, unsigned& r1, unsigned& r2, unsigned& r3,
                                      const unsigned* p) {
    unsigned a = (unsigned)__cvta_generic_to_shared(p);
    asm volatile("ldmatrix.sync.aligned.m8n8.x4.shared.b16 {%0,%1,%2,%3},[%4];"
        : "=r"(r0), "=r"(r1), "=r"(r2), "=r"(r3) : "r"(a));
}

__device__ __forceinline__ void cpa16(unsigned* dst, const void* src) {
    unsigned d = (unsigned)__cvta_generic_to_shared(dst);
    asm volatile("cp.async.ca.shared.global [%0], [%1], 16;" :: "r"(d), "l"(src));
}
#define CP_COMMIT() asm volatile("cp.async.commit_group;")
#define CP_WAIT(N)  asm volatile("cp.async.wait_group %0;" :: "n"(N))

// 128B-row swizzles: full 8-group XOR -> conflict-free STS/LDGSTS.128 and LDSM
__device__ __forceinline__ int sw32(int m, int k) {   // rows of 32 floats
    return m*32 + (((((k) >> 2) ^ (m & 7)) << 2) | (k & 3));
}
__device__ __forceinline__ int sw64(int r, int c) {   // rows of 64 floats
    return r*64 + (((((c) >> 2) ^ (r & 7)) << 2) | (c & 3));
}

#define BK     32
#define TBUF   (128*BK)
#define STG    (2*TBUF)
#define NSTAGE 3
#define GEMM_SMEM_BYTES (NSTAGE * STG * (int)sizeof(unsigned))   // 96KB

// ============ kernel 0: tf32 pre-conversion ============
__global__ __launch_bounds__(256) void prep_kernel(const float* __restrict__ src,
                                                   float* __restrict__ dst, int n4)
{
    int i = blockIdx.x * blockDim.x + threadIdx.x;
    if (i < n4) {
        float4 v = ((const float4*)src)[i];
        v.x = f2tff(v.x); v.y = f2tff(v.y); v.z = f2tff(v.z); v.w = f2tff(v.w);
        ((float4*)dst)[i] = v;
    }
}

__global__ __launch_bounds__(256) void prep_w_kernel(
    const float* __restrict__ w0, const float* __restrict__ w1,
    const float* __restrict__ w2, const float* __restrict__ w3,
    float* __restrict__ d0, float* __restrict__ d1,
    float* __restrict__ d2, float* __restrict__ d3)
{
    int z = blockIdx.z;
    const float* src = (z == 0) ? w0 : (z == 1 ? w1 : (z == 2 ? w2 : w3));
    float* dst       = (z == 0) ? d0 : (z == 1 ? d1 : (z == 2 ? d2 : d3));
    int i = blockIdx.x * blockDim.x + threadIdx.x;
    float4 v = ((const float4*)src)[i];
    v.x = f2tff(v.x); v.y = f2tff(v.y); v.z = f2tff(v.z); v.w = f2tff(v.w);
    ((float4*)dst)[i] = v;
}

// ============ 128x128 NT GEMM core, cp.async 3-stage pipeline ============
// 128 threads = 4 warps in 2(m) x 2(n); warp tile 64x64 = 4 mtiles x 8 ntiles.
__device__ __forceinline__ void gemm_core(
    const float* __restrict__ A, const float* __restrict__ W,
    int row0, int col0, unsigned* smem, float acc[4][8][4])
{
    const int K = EMBED;
    int tid  = threadIdx.x;
    int lane = tid & 31, wid = tid >> 5;
    int wm = wid >> 1, wn = wid & 1;

    #pragma unroll
    for (int mt = 0; mt < 4; mt++)
        #pragma unroll
        for (int nt = 0; nt < 8; nt++)
            #pragma unroll
            for (int i = 0; i < 4; i++) acc[mt][nt][i] = 0.f;

    int fr[8], fc[8];
    #pragma unroll
    for (int i = 0; i < 8; i++) { int f = tid + 128*i; fr[i] = f >> 3; fc[i] = (f & 7) * 4; }

    int offA[4][4], offB[4][4];
    {
        int eA = (lane & 16) ? 4 : 0;
        int eB = (lane & 8)  ? 4 : 0;
        #pragma unroll
        for (int mt = 0; mt < 4; mt++) {
            int r = wm*64 + mt*16 + (lane & 15);
            #pragma unroll
            for (int s = 0; s < 4; s++) offA[mt][s] = sw32(r, s*8 + eA);
        }
        #pragma unroll
        for (int p = 0; p < 4; p++) {
            int r = wn*64 + p*16 + (lane & 7) + ((lane >> 4) & 1) * 8;
            #pragma unroll
            for (int s = 0; s < 4; s++) offB[p][s] = sw32(r, s*8 + eB);
        }
    }

    const float* Abase = A + (size_t)row0 * K;
    const float* Bbase = W + (size_t)col0 * K;

    auto issue = [&](int kt) {
        unsigned* st = smem + (kt % NSTAGE) * STG;
        const float* Ab = Abase + kt * BK;
        const float* Bb = Bbase + kt * BK;
        #pragma unroll
        for (int i = 0; i < 8; i++)
            cpa16(st + sw32(fr[i], fc[i]), Ab + (size_t)fr[i] * K + fc[i]);
        #pragma unroll
        for (int i = 0; i < 8; i++)
            cpa16(st + TBUF + sw32(fr[i], fc[i]), Bb + (size_t)fr[i] * K + fc[i]);
        CP_COMMIT();
    };

    const int NK = K / BK;   // 32
    issue(0); issue(1);
    for (int kt = 0; kt < NK; kt++) {
        if (kt + 1 < NK) { CP_WAIT(1); } else { CP_WAIT(0); }
        __syncthreads();
        if (kt + 2 < NK) issue(kt + 2);
        const unsigned* Ab = smem + (kt % NSTAGE) * STG;
        const unsigned* Bb = Ab + TBUF;
        #pragma unroll
        for (int s = 0; s < 4; s++) {
            unsigned a[4][4], b[8][2];
            #pragma unroll
            for (int mt = 0; mt < 4; mt++)
                ldsm4(a[mt][0], a[mt][1], a[mt][2], a[mt][3], Ab + offA[mt][s]);
            #pragma unroll
            for (int p = 0; p < 4; p++)
                ldsm4(b[2*p][0], b[2*p][1], b[2*p+1][0], b[2*p+1][1], Bb + offB[p][s]);
            #pragma unroll
            for (int mt = 0; mt < 4; mt++)
                #pragma unroll
                for (int nt = 0; nt < 8; nt++)
                    mma8(acc[mt][nt], a[mt], b[nt]);
        }
    }
}

// ============ Kernel 1: fused QKV projections (grid.z picks Q/K/V) ============
__global__ __launch_bounds__(128, 2) void qkv_kernel()
{
    extern __shared__ __align__(16) unsigned smem[];
    int row0 = blockIdx.y * 128, col0 = blockIdx.x * 128;
    int z = blockIdx.z;
    const float* W = (z == 0) ? g_wq : (z == 1 ? g_wk : g_wv);
    float scale    = (z == 0) ? 0.125f : 1.0f;

    float acc[4][8][4];
    gemm_core(g_x, W, row0, col0, smem, acc);

    int lane = threadIdx.x & 31, wid = threadIdx.x >> 5;
    int g = lane >> 2, tg = lane & 3, wm = wid >> 1, wn = wid & 1;
    #pragma unroll
    for (int mt = 0; mt < 4; mt++) {
        int r = row0 + wm*64 + mt*16 + g;
        int bb = r >> 11, ss = r & 2047;
        #pragma unroll
        for (int nt = 0; nt < 8; nt++) {
            int c = col0 + wn*64 + nt*8 + 2*tg;
            int h = c >> 6, d = c & 63;
            if (z == 2) {
                float* pv = g_v + (((size_t)(bb*NHEAD + h) * DK + d) * SEQ + ss);
                pv[0]       = f2tff(acc[mt][nt][0]);
                pv[SEQ]     = f2tff(acc[mt][nt][1]);
                pv[8]       = f2tff(acc[mt][nt][2]);
                pv[SEQ + 8] = f2tff(acc[mt][nt][3]);
            } else {
                float* dst = (z == 0) ? g_q : g_k;
                float* p0 = dst + (((size_t)(bb*NHEAD + h) * SEQ + ss) * DK + d);
                float* p1 = p0 + 8*DK;
                p0[0] = f2tff(acc[mt][nt][0] * scale); p0[1] = f2tff(acc[mt][nt][1] * scale);
                p1[0] = f2tff(acc[mt][nt][2] * scale); p1[1] = f2tff(acc[mt][nt][3] * scale);
            }
        }
    }
}

// ============ Kernel 2: flash attention, 128q CTA, 32q/warp, no P smem ============
// 128 threads = 4 warps; warp owns 32 q rows as two 16-row groups (u=0,1).
// P A-fragments built by quad shuffles from the S accumulator fragment.
// smem: [Qs 32KB][K0 16|V0 16|K1 16|V1 16] = 96KB -> 2 CTA/SM.
#define ATTN_SMEM_BYTES ((8192 + 16384) * (int)sizeof(unsigned))
__global__ __launch_bounds__(128, 2) void attn_kernel()
{
    extern __shared__ __align__(16) unsigned asm_[];
    unsigned* Qs = asm_;             // 128 x 64
    unsigned* KV = asm_ + 8192;      // stage s: K at s*8192, Vt at s*8192+4096

    int qt = blockIdx.x, bh = blockIdx.y;
    const float* Qp = g_q + (size_t)bh * SEQ * DK + (size_t)qt * 128 * DK;
    const float* Kp = g_k + (size_t)bh * SEQ * DK;
    const float* Vp = g_v + (size_t)bh * DK * SEQ;   // [d, s]

    int tid = threadIdx.x, lane = tid & 31, wid = tid >> 5;
    int g = lane >> 2, tg = lane & 3;

    int eA = (lane & 16) ? 4 : 0;
    int rA0 = wid*32 + (lane & 15);          // group 0 A rows
    int eB = (lane & 8)  ? 4 : 0;
    int rB[4];
    #pragma unroll
    for (int p = 0; p < 4; p++) rB[p] = p*16 + (lane & 7) + ((lane >> 4) & 1) * 8;

    // shuffle source lanes for P A-fragment construction (quad-local)
    int sl0 = 4*g + (tg >> 1);        // cols tg   (a[0], a[1])
    int sl1 = sl0 + 2;                // cols tg+4 (a[2], a[3])
    bool odd = (tg & 1);

    // K/V fill addresses (64-row tiles, 128 threads -> 8 float4 each)
    int adKV[8], goffK[8], goffV[8];
    #pragma unroll
    for (int i = 0; i < 8; i++) {
        int f = tid + 128*i;
        int r = f >> 4, c4 = f & 15;
        adKV[i]  = r*64 + ((c4 ^ (r & 7)) << 2);
        goffK[i] = r*64 + c4*4;
        goffV[i] = r*SEQ + c4*4;
    }

    // Q fill (128 rows x 64, 16 float4 per thread)
    #pragma unroll
    for (int i = 0; i < 16; i++) {
        int f = tid + 128*i;
        int r = f >> 4, c4 = f & 15;
        cpa16(Qs + r*64 + ((c4 ^ (r & 7)) << 2), Qp + r*64 + c4*4);
    }
    CP_COMMIT();
    // first K/Vt tile
    #pragma unroll
    for (int i = 0; i < 8; i++) {
        cpa16(KV + adKV[i],        Kp + goffK[i]);
        cpa16(KV + 4096 + adKV[i], Vp + goffV[i]);
    }
    CP_COMMIT();

    float o[2][8][4];
    #pragma unroll
    for (int u = 0; u < 2; u++)
        #pragma unroll
        for (int nt = 0; nt < 8; nt++)
            #pragma unroll
            for (int i = 0; i < 4; i++) o[u][nt][i] = 0.f;
    float m0[2] = {-1e30f, -1e30f}, m1[2] = {-1e30f, -1e30f};
    float l0[2] = {0.f, 0.f},       l1[2] = {0.f, 0.f};

    const int NT = SEQ/64;
    for (int kt = 0; kt < NT; kt++) {
        CP_WAIT(0);
        __syncthreads();

        if (kt + 1 < NT) {
            unsigned* st = KV + ((kt + 1) & 1) * 8192;
            int t = (kt + 1) * 64;
            #pragma unroll
            for (int i = 0; i < 8; i++) {
                cpa16(st + adKV[i],        Kp + (size_t)t * DK + goffK[i]);
                cpa16(st + 4096 + adKV[i], Vp + t + goffV[i]);
            }
            CP_COMMIT();
        }

        const unsigned* Ks  = KV + (kt & 1) * 8192;
        const unsigned* Vts = Ks + 4096;

        // S = Q * K^T   (two 16-row groups share every B fragment)
        float s[2][8][4];
        #pragma unroll
        for (int u = 0; u < 2; u++)
            #pragma unroll
            for (int nt = 0; nt < 8; nt++)
                #pragma unroll
                for (int i = 0; i < 4; i++) s[u][nt][i] = 0.f;
        #pragma unroll
        for (int kk8 = 0; kk8 < 8; kk8++) {
            unsigned a0[4], a1[4], b[8][2];
            ldsm4(a0[0], a0[1], a0[2], a0[3], Qs + sw64(rA0,      kk8*8 + eA));
            ldsm4(a1[0], a1[1], a1[2], a1[3], Qs + sw64(rA0 + 16, kk8*8 + eA));
            #pragma unroll
            for (int p = 0; p < 4; p++)
                ldsm4(b[2*p][0], b[2*p][1], b[2*p+1][0], b[2*p+1][1],
                      Ks + sw64(rB[p], kk8*8 + eB));
            #pragma unroll
            for (int nt = 0; nt < 8; nt++) mma8(s[0][nt], a0, b[nt]);
            #pragma unroll
            for (int nt = 0; nt < 8; nt++) mma8(s[1][nt], a1, b[nt]);
        }

        // online softmax per group
        #pragma unroll
        for (int u = 0; u < 2; u++) {
            float ml0 = -1e30f, ml1 = -1e30f;
            #pragma unroll
            for (int nt = 0; nt < 8; nt++) {
                ml0 = fmaxf(ml0, fmaxf(s[u][nt][0], s[u][nt][1]));
                ml1 = fmaxf(ml1, fmaxf(s[u][nt][2], s[u][nt][3]));
            }
            ml0 = fmaxf(ml0, __shfl_xor_sync(0xffffffffu, ml0, 1));
            ml0 = fmaxf(ml0, __shfl_xor_sync(0xffffffffu, ml0, 2));
            ml1 = fmaxf(ml1, __shfl_xor_sync(0xffffffffu, ml1, 1));
            ml1 = fmaxf(ml1, __shfl_xor_sync(0xffffffffu, ml1, 2));
            float mn0 = fmaxf(m0[u], ml0), mn1 = fmaxf(m1[u], ml1);
            float al0 = __expf(m0[u] - mn0), al1 = __expf(m1[u] - mn1);
            m0[u] = mn0; m1[u] = mn1;
            float sum0 = 0.f, sum1 = 0.f;
            #pragma unroll
            for (int nt = 0; nt < 8; nt++) {
                s[u][nt][0] = __expf(s[u][nt][0] - mn0); sum0 += s[u][nt][0];
                s[u][nt][1] = __expf(s[u][nt][1] - mn0); sum0 += s[u][nt][1];
                s[u][nt][2] = __expf(s[u][nt][2] - mn1); sum1 += s[u][nt][2];
                s[u][nt][3] = __expf(s[u][nt][3] - mn1); sum1 += s[u][nt][3];
            }
            sum0 += __shfl_xor_sync(0xffffffffu, sum0, 1);
            sum0 += __shfl_xor_sync(0xffffffffu, sum0, 2);
            sum1 += __shfl_xor_sync(0xffffffffu, sum1, 1);
            sum1 += __shfl_xor_sync(0xffffffffu, sum1, 2);
            l0[u] = l0[u] * al0 + sum0;
            l1[u] = l1[u] * al1 + sum1;
            #pragma unroll
            for (int nt = 0; nt < 8; nt++) {
                o[u][nt][0] *= al0; o[u][nt][1] *= al0;
                o[u][nt][2] *= al1; o[u][nt][3] *= al1;
            }
        }

        // O += P * V : P A-frags via quad shuffles from s[u][kk8][*]
        #pragma unroll
        for (int kk8 = 0; kk8 < 8; kk8++) {
            unsigned b[8][2];
            #pragma unroll
            for (int p = 0; p < 4; p++)
                ldsm4(b[2*p][0], b[2*p][1], b[2*p+1][0], b[2*p+1][1],
                      Vts + sw64(rB[p], kk8*8 + eB));
            #pragma unroll
            for (int u = 0; u < 2; u++) {
                float v0 = __shfl_sync(0xffffffffu, s[u][kk8][0], sl0);
                float v1 = __shfl_sync(0xffffffffu, s[u][kk8][1], sl0);
                float v2 = __shfl_sync(0xffffffffu, s[u][kk8][2], sl0);
                float v3 = __shfl_sync(0xffffffffu, s[u][kk8][3], sl0);
                float v4 = __shfl_sync(0xffffffffu, s[u][kk8][0], sl1);
                float v5 = __shfl_sync(0xffffffffu, s[u][kk8][1], sl1);
                float v6 = __shfl_sync(0xffffffffu, s[u][kk8][2], sl1);
                float v7 = __shfl_sync(0xffffffffu, s[u][kk8][3], sl1);
                unsigned a[4];
                a[0] = f2tf(odd ? v1 : v0);
                a[1] = f2tf(odd ? v3 : v2);
                a[2] = f2tf(odd ? v5 : v4);
                a[3] = f2tf(odd ? v7 : v6);
                #pragma unroll
                for (int nt = 0; nt < 8; nt++) mma8(o[u][nt], a, b[nt]);
            }
        }
    }

    // epilogue per group
    int bb = bh >> 4, h = bh & 15;
    #pragma unroll
    for (int u = 0; u < 2; u++) {
        float inv0 = 1.f / l0[u], inv1 = 1.f / l1[u];
        int q0 = qt*128 + wid*32 + u*16 + g;
        float* base0 = g_attn + ((size_t)(bb*SEQ + q0) * EMBED) + h*64;
        float* base1 = base0 + (size_t)8 * EMBED;
        #pragma unroll
        for (int nt = 0; nt < 8; nt++) {
            int d = nt*8 + 2*tg;
            base0[d]     = f2tff(o[u][nt][0] * inv0);
            base0[d + 1] = f2tff(o[u][nt][1] * inv0);
            base1[d]     = f2tff(o[u][nt][2] * inv1);
            base1[d + 1] = f2tff(o[u][nt][3] * inv1);
        }
    }
}

// ============ Kernel 3: output projection ============
__global__ __launch_bounds__(128, 2) void oproj_kernel(float* __restrict__ out)
{
    extern __shared__ __align__(16) unsigned smem[];
    int row0 = blockIdx.y * 128, col0 = blockIdx.x * 128;
    float acc[4][8][4];
    gemm_core(g_attn, g_wo, row0, col0, smem, acc);

    int lane = threadIdx.x & 31, wid = threadIdx.x >> 5;
    int g = lane >> 2, tg = lane & 3, wm = wid >> 1, wn = wid & 1;
    #pragma unroll
    for (int mt = 0; mt < 4; mt++) {
        int r = row0 + wm*64 + mt*16 + g;
        #pragma unroll
        for (int nt = 0; nt < 8; nt++) {
            int c = col0 + wn*64 + nt*8 + 2*tg;
            float* p0 = out + (size_t)r * EMBED + c;
            float* p1 = out + (size_t)(r + 8) * EMBED + c;
            p0[0] = acc[mt][nt][0]; p0[1] = acc[mt][nt][1];
            p1[0] = acc[mt][nt][2]; p1[1] = acc[mt][nt][3];
        }
    }
}

// ============ launch ============
extern "C" void kernel_launch(void* const* d_in, const int* in_sizes, int n_in,
                              void* d_out, int out_size)
{
    const float* x  = (const float*)d_in[0];
    const float* Wq = (const float*)d_in[1];
    const float* Wk = (const float*)d_in[2];
    const float* Wv = (const float*)d_in[3];
    const float* Wo = (const float*)d_in[4];
    float* out = (float*)d_out;

    cudaFuncSetAttribute(qkv_kernel,   cudaFuncAttributeMaxDynamicSharedMemorySize, GEMM_SMEM_BYTES);
    cudaFuncSetAttribute(oproj_kernel, cudaFuncAttributeMaxDynamicSharedMemorySize, GEMM_SMEM_BYTES);
    cudaFuncSetAttribute(attn_kernel,  cudaFuncAttributeMaxDynamicSharedMemorySize, ATTN_SMEM_BYTES);

    float* p_x;  cudaGetSymbolAddress((void**)&p_x,  g_x);
    float* p_wq; cudaGetSymbolAddress((void**)&p_wq, g_wq);
    float* p_wk; cudaGetSymbolAddress((void**)&p_wk, g_wk);
    float* p_wv; cudaGetSymbolAddress((void**)&p_wv, g_wv);
    float* p_wo; cudaGetSymbolAddress((void**)&p_wo, g_wo);

    int nx4 = MTOK*EMBED/4, nw4 = EMBED*EMBED/4;
    prep_kernel<<<(nx4 + 255)/256, 256>>>(x, p_x, nx4);
    prep_w_kernel<<<dim3(nw4/256, 1, 4), 256>>>(Wq, Wk, Wv, Wo, p_wq, p_wk, p_wv, p_wo);

    qkv_kernel<<<dim3(EMBED/128, MTOK/128, 3), 128, GEMM_SMEM_BYTES>>>();
    attn_kernel<<<dim3(SEQ/128, BATCH*NHEAD), 128, ATTN_SMEM_BYTES>>>();
    oproj_kernel<<<dim3(EMBED/128, MTOK/128), 128, GEMM_SMEM_BYTES>>>(out);
}

// round 14
// speedup vs baseline: 2.2474x; 1.9618x over previous
#include <cuda_runtime.h>
#include <cuda_fp16.h>
#include <math.h>

#define EMBED 1024
#define NHEAD 16
#define DK    64
#define BATCH 4
#define SEQ   2048
#define MTOK  (BATCH*SEQ)   // 8192
#define LOG2E 1.44269504f

// -------- scratch (device globals; no allocation allowed) --------
__device__ __half g_x [(size_t)MTOK*EMBED];
__device__ __half g_wq[(size_t)EMBED*EMBED];
__device__ __half g_wk[(size_t)EMBED*EMBED];
__device__ __half g_wv[(size_t)EMBED*EMBED];
__device__ __half g_wo[(size_t)EMBED*EMBED];
__device__ __half g_q[(size_t)BATCH*NHEAD*SEQ*DK];   // [b,h,s,d], pre-scaled by log2e/8
__device__ __half g_k[(size_t)BATCH*NHEAD*SEQ*DK];   // [b,h,s,d]
__device__ __half g_v[(size_t)BATCH*NHEAD*DK*SEQ];   // [b,h,d,s]  (TRANSPOSED)
__device__ __half g_attn[(size_t)MTOK*EMBED];

// -------- helpers --------
__device__ __forceinline__ float ex2(float x) {
    float r; asm("ex2.approx.f32 %0, %1;" : "=f"(r) : "f"(x)); return r;
}
__device__ __forceinline__ unsigned packh2(float a, float b) {
    __half2 h = __floats2half2_rn(a, b);
    return *(unsigned*)&h;
}

__device__ __forceinline__ void mma16h(float* c, const unsigned* a, const unsigned* b) {
    asm volatile("mma.sync.aligned.m16n8k16.row.col.f32.f16.f16.f32 "
        "{%0,%1,%2,%3},{%4,%5,%6,%7},{%8,%9},{%0,%1,%2,%3};"
        : "+f"(c[0]), "+f"(c[1]), "+f"(c[2]), "+f"(c[3])
        : "r"(a[0]), "r"(a[1]), "r"(a[2]), "r"(a[3]), "r"(b[0]), "r"(b[1]));
}

__device__ __forceinline__ void ldsm4(unsigned& r0, unsigned& r1, unsigned& r2, unsigned& r3,
                                      const void* p) {
    unsigned a = (unsigned)__cvta_generic_to_shared(p);
    asm volatile("ldmatrix.sync.aligned.m8n8.x4.shared.b16 {%0,%1,%2,%3},[%4];"
        : "=r"(r0), "=r"(r1), "=r"(r2), "=r"(r3) : "r"(a));
}

__device__ __forceinline__ void cpa16(void* dst, const void* src) {
    unsigned d = (unsigned)__cvta_generic_to_shared(dst);
    asm volatile("cp.async.ca.shared.global [%0], [%1], 16;" :: "r"(d), "l"(src));
}
#define CP_COMMIT() asm volatile("cp.async.commit_group;")
#define CP_WAIT(N)  asm volatile("cp.async.wait_group %0;" :: "n"(N))

// 128B-row swizzle for half tiles of row-width 64 halves (16B groups, full 8-XOR)
__device__ __forceinline__ int swH(int r, int c) {
    return r*64 + (((((c) >> 3) ^ (r & 7)) << 3) | (c & 7));
}

#define BKH    64                 // k-halves per GEMM tile
#define TBUFH  (128*64)           // halves per A (or B) tile = 16KB
#define STGH   (2*TBUFH)
#define NSTAGE 3
#define GEMM_SMEM_BYTES (NSTAGE * STGH * (int)sizeof(__half))   // 96KB

// ============ kernel 0: fp16 pre-conversion (8 elems/thread) ============
__global__ __launch_bounds__(256) void prep_kernel(const float* __restrict__ src,
                                                   __half* __restrict__ dst, int n8)
{
    int i = blockIdx.x * blockDim.x + threadIdx.x;
    if (i < n8) {
        float4 v0 = ((const float4*)src)[2*i];
        float4 v1 = ((const float4*)src)[2*i + 1];
        uint4 o;
        o.x = packh2(v0.x, v0.y); o.y = packh2(v0.z, v0.w);
        o.z = packh2(v1.x, v1.y); o.w = packh2(v1.z, v1.w);
        ((uint4*)dst)[i] = o;
    }
}

__global__ __launch_bounds__(256) void prep_w_kernel(
    const float* __restrict__ w0, const float* __restrict__ w1,
    const float* __restrict__ w2, const float* __restrict__ w3,
    __half* __restrict__ d0, __half* __restrict__ d1,
    __half* __restrict__ d2, __half* __restrict__ d3)
{
    int z = blockIdx.z;
    const float* src = (z == 0) ? w0 : (z == 1 ? w1 : (z == 2 ? w2 : w3));
    __half* dst      = (z == 0) ? d0 : (z == 1 ? d1 : (z == 2 ? d2 : d3));
    int i = blockIdx.x * blockDim.x + threadIdx.x;
    float4 v0 = ((const float4*)src)[2*i];
    float4 v1 = ((const float4*)src)[2*i + 1];
    uint4 o;
    o.x = packh2(v0.x, v0.y); o.y = packh2(v0.z, v0.w);
    o.z = packh2(v1.x, v1.y); o.w = packh2(v1.z, v1.w);
    ((uint4*)dst)[i] = o;
}

// ============ 128x128 NT GEMM core (fp16, K=1024), cp.async 3-stage ============
// 128 threads = 4 warps (2m x 2n); warp tile 64x64; mma m16n8k16.
__device__ __forceinline__ void gemm_core(
    const __half* __restrict__ A, const __half* __restrict__ W,
    int row0, int col0, __half* smem, float acc[4][8][4])
{
    const int K = EMBED;
    int tid  = threadIdx.x;
    int lane = tid & 31, wid = tid >> 5;
    int wm = wid >> 1, wn = wid & 1;

    #pragma unroll
    for (int mt = 0; mt < 4; mt++)
        #pragma unroll
        for (int nt = 0; nt < 8; nt++)
            #pragma unroll
            for (int i = 0; i < 4; i++) acc[mt][nt][i] = 0.f;

    int fr[8], fcH[8];
    #pragma unroll
    for (int i = 0; i < 8; i++) { int f = tid + 128*i; fr[i] = f >> 3; fcH[i] = (f & 7) * 8; }

    int offA[4][4], offB[4][4];
    {
        int eA = ((lane >> 4) & 1) * 8;          // A: k+8 halves for lanes>=16
        int eB = ((lane >> 3) & 1) * 8;          // B: k+8 halves for lanes 8-15,24-31
        #pragma unroll
        for (int mt = 0; mt < 4; mt++) {
            int r = wm*64 + mt*16 + (lane & 15);
            #pragma unroll
            for (int s = 0; s < 4; s++) offA[mt][s] = swH(r, s*16 + eA);
        }
        #pragma unroll
        for (int p = 0; p < 4; p++) {
            int r = wn*64 + p*16 + (lane & 7) + ((lane >> 4) & 1) * 8;
            #pragma unroll
            for (int s = 0; s < 4; s++) offB[p][s] = swH(r, s*16 + eB);
        }
    }

    const __half* Abase = A + (size_t)row0 * K;
    const __half* Bbase = W + (size_t)col0 * K;

    auto issue = [&](int kt) {
        __half* st = smem + (kt % NSTAGE) * STGH;
        const __half* Ab = Abase + kt * BKH;
        const __half* Bb = Bbase + kt * BKH;
        #pragma unroll
        for (int i = 0; i < 8; i++)
            cpa16(st + swH(fr[i], fcH[i]), Ab + (size_t)fr[i] * K + fcH[i]);
        #pragma unroll
        for (int i = 0; i < 8; i++)
            cpa16(st + TBUFH + swH(fr[i], fcH[i]), Bb + (size_t)fr[i] * K + fcH[i]);
        CP_COMMIT();
    };

    const int NK = K / BKH;   // 16
    issue(0); issue(1);
    for (int kt = 0; kt < NK; kt++) {
        if (kt + 1 < NK) { CP_WAIT(1); } else { CP_WAIT(0); }
        __syncthreads();
        if (kt + 2 < NK) issue(kt + 2);
        const __half* Ab = smem + (kt % NSTAGE) * STGH;
        const __half* Bb = Ab + TBUFH;
        #pragma unroll
        for (int s = 0; s < 4; s++) {
            unsigned a[4][4], b[8][2];
            #pragma unroll
            for (int mt = 0; mt < 4; mt++)
                ldsm4(a[mt][0], a[mt][1], a[mt][2], a[mt][3], Ab + offA[mt][s]);
            #pragma unroll
            for (int p = 0; p < 4; p++)
                ldsm4(b[2*p][0], b[2*p][1], b[2*p+1][0], b[2*p+1][1], Bb + offB[p][s]);
            #pragma unroll
            for (int mt = 0; mt < 4; mt++)
                #pragma unroll
                for (int nt = 0; nt < 8; nt++)
                    mma16h(acc[mt][nt], a[mt], b[nt]);
        }
    }
}

// ============ Kernel 1: fused QKV projections (grid.z picks Q/K/V) ============
__global__ __launch_bounds__(128, 2) void qkv_kernel()
{
    extern __shared__ __align__(16) __half smem[];
    int row0 = blockIdx.y * 128, col0 = blockIdx.x * 128;
    int z = blockIdx.z;
    const __half* W = (z == 0) ? g_wq : (z == 1 ? g_wk : g_wv);
    float scale     = (z == 0) ? 0.125f * LOG2E : 1.0f;   // 1/sqrt(64) * log2(e) folded

    float acc[4][8][4];
    gemm_core(g_x, W, row0, col0, smem, acc);

    int lane = threadIdx.x & 31, wid = threadIdx.x >> 5;
    int g = lane >> 2, tg = lane & 3, wm = wid >> 1, wn = wid & 1;
    #pragma unroll
    for (int mt = 0; mt < 4; mt++) {
        int r = row0 + wm*64 + mt*16 + g;
        int bb = r >> 11, ss = r & 2047;
        #pragma unroll
        for (int nt = 0; nt < 8; nt++) {
            int c = col0 + wn*64 + nt*8 + 2*tg;
            int h = c >> 6, d = c & 63;
            if (z == 2) {
                __half* pv = g_v + (((size_t)(bb*NHEAD + h) * DK + d) * SEQ + ss);
                pv[0]       = __float2half_rn(acc[mt][nt][0]);
                pv[SEQ]     = __float2half_rn(acc[mt][nt][1]);
                pv[8]       = __float2half_rn(acc[mt][nt][2]);
                pv[SEQ + 8] = __float2half_rn(acc[mt][nt][3]);
            } else {
                __half* dst = (z == 0) ? g_q : g_k;
                __half* p0 = dst + (((size_t)(bb*NHEAD + h) * SEQ + ss) * DK + d);
                __half* p1 = p0 + 8*DK;
                *(__half2*)p0 = __floats2half2_rn(acc[mt][nt][0] * scale, acc[mt][nt][1] * scale);
                *(__half2*)p1 = __floats2half2_rn(acc[mt][nt][2] * scale, acc[mt][nt][3] * scale);
            }
        }
    }
}

// ============ Kernel 2: flash attention (fp16), 128q CTA, 32q/warp ============
// Q frags hoisted (32 regs); P never leaves registers (C->A fragment identity).
// smem: Qs 16KB + 2 KV stages x (K 8K + V 8K) = 48KB.
#define ATTN_SMEM_BYTES ((8192 + 2*8192) * (int)sizeof(__half))
__global__ __launch_bounds__(128, 2) void attn_kernel()
{
    extern __shared__ __align__(16) __half asm_[];
    __half* Qs = asm_;               // 128 x 64 halves
    __half* KV = asm_ + 8192;        // stage s at s*8192: K 4096H, V 4096H

    int qt = blockIdx.x, bh = blockIdx.y;
    const __half* Qp = g_q + (size_t)bh * SEQ * DK + (size_t)qt * 128 * DK;
    const __half* Kp = g_k + (size_t)bh * SEQ * DK;
    const __half* Vp = g_v + (size_t)bh * DK * SEQ;   // [d, s]

    int tid = threadIdx.x, lane = tid & 31, wid = tid >> 5;
    int g = lane >> 2, tg = lane & 3;

    int eA = ((lane >> 4) & 1) * 8;
    int rA0 = wid*32 + (lane & 15);
    int eB = ((lane >> 3) & 1) * 8;
    int rB[4];
    #pragma unroll
    for (int p = 0; p < 4; p++) rB[p] = p*16 + (lane & 7) + ((lane >> 4) & 1) * 8;

    // K/V fill (64 rows x 64H = 512 chunks -> 4/thread)
    int adKV[4], goffK[4], goffV[4];
    #pragma unroll
    for (int i = 0; i < 4; i++) {
        int f = tid + 128*i;
        int r = f >> 3, c8 = (f & 7) * 8;
        adKV[i]  = swH(r, c8);
        goffK[i] = r*64 + c8;
        goffV[i] = r*SEQ + c8;
    }

    // Q fill (128 rows x 64H = 1024 chunks -> 8/thread)
    #pragma unroll
    for (int i = 0; i < 8; i++) {
        int f = tid + 128*i;
        int r = f >> 3, c8 = (f & 7) * 8;
        cpa16(Qs + swH(r, c8), Qp + r*64 + c8);
    }
    CP_COMMIT();
    #pragma unroll
    for (int i = 0; i < 4; i++) {
        cpa16(KV + adKV[i],        Kp + goffK[i]);
        cpa16(KV + 4096 + adKV[i], Vp + goffV[i]);
    }
    CP_COMMIT();

    // hoist Q fragments: [u][kstep][4]
    unsigned qf[2][4][4];
    CP_WAIT(1);
    __syncthreads();
    #pragma unroll
    for (int u = 0; u < 2; u++)
        #pragma unroll
        for (int ks = 0; ks < 4; ks++)
            ldsm4(qf[u][ks][0], qf[u][ks][1], qf[u][ks][2], qf[u][ks][3],
                  Qs + swH(rA0 + u*16, ks*16 + eA));

    float o[2][8][4];
    #pragma unroll
    for (int u = 0; u < 2; u++)
        #pragma unroll
        for (int nt = 0; nt < 8; nt++)
            #pragma unroll
            for (int i = 0; i < 4; i++) o[u][nt][i] = 0.f;
    float m0[2] = {-1e30f, -1e30f}, m1[2] = {-1e30f, -1e30f};
    float l0[2] = {0.f, 0.f},       l1[2] = {0.f, 0.f};

    const int NT = SEQ/64;
    for (int kt = 0; kt < NT; kt++) {
        CP_WAIT(0);
        __syncthreads();

        if (kt + 1 < NT) {
            __half* st = KV + ((kt + 1) & 1) * 8192;
            int t = (kt + 1) * 64;
            #pragma unroll
            for (int i = 0; i < 4; i++) {
                cpa16(st + adKV[i],        Kp + (size_t)t * DK + goffK[i]);
                cpa16(st + 4096 + adKV[i], Vp + t + goffV[i]);
            }
            CP_COMMIT();
        }

        const __half* Ks  = KV + (kt & 1) * 8192;
        const __half* Vts = Ks + 4096;

        // S = Q * K^T  (logits already scaled by log2e/8)
        float s[2][8][4];
        #pragma unroll
        for (int u = 0; u < 2; u++)
            #pragma unroll
            for (int nt = 0; nt < 8; nt++)
                #pragma unroll
                for (int i = 0; i < 4; i++) s[u][nt][i] = 0.f;
        #pragma unroll
        for (int ks = 0; ks < 4; ks++) {
            unsigned b[8][2];
            #pragma unroll
            for (int p = 0; p < 4; p++)
                ldsm4(b[2*p][0], b[2*p][1], b[2*p+1][0], b[2*p+1][1],
                      Ks + swH(rB[p], ks*16 + eB));
            #pragma unroll
            for (int nt = 0; nt < 8; nt++) mma16h(s[0][nt], qf[0][ks], b[nt]);
            #pragma unroll
            for (int nt = 0; nt < 8; nt++) mma16h(s[1][nt], qf[1][ks], b[nt]);
        }

        // online softmax (base-2)
        #pragma unroll
        for (int u = 0; u < 2; u++) {
            float ml0 = -1e30f, ml1 = -1e30f;
            #pragma unroll
            for (int nt = 0; nt < 8; nt++) {
                ml0 = fmaxf(ml0, fmaxf(s[u][nt][0], s[u][nt][1]));
                ml1 = fmaxf(ml1, fmaxf(s[u][nt][2], s[u][nt][3]));
            }
            ml0 = fmaxf(ml0, __shfl_xor_sync(0xffffffffu, ml0, 1));
            ml0 = fmaxf(ml0, __shfl_xor_sync(0xffffffffu, ml0, 2));
            ml1 = fmaxf(ml1, __shfl_xor_sync(0xffffffffu, ml1, 1));
            ml1 = fmaxf(ml1, __shfl_xor_sync(0xffffffffu, ml1, 2));
            float mn0 = fmaxf(m0[u], ml0), mn1 = fmaxf(m1[u], ml1);
            float al0 = ex2(m0[u] - mn0), al1 = ex2(m1[u] - mn1);
            m0[u] = mn0; m1[u] = mn1;
            float sum0 = 0.f, sum1 = 0.f;
            #pragma unroll
            for (int nt = 0; nt < 8; nt++) {
                s[u][nt][0] = ex2(s[u][nt][0] - mn0); sum0 += s[u][nt][0];
                s[u][nt][1] = ex2(s[u][nt][1] - mn0); sum0 += s[u][nt][1];
                s[u][nt][2] = ex2(s[u][nt][2] - mn1); sum1 += s[u][nt][2];
                s[u][nt][3] = ex2(s[u][nt][3] - mn1); sum1 += s[u][nt][3];
            }
            sum0 += __shfl_xor_sync(0xffffffffu, sum0, 1);
            sum0 += __shfl_xor_sync(0xffffffffu, sum0, 2);
            sum1 += __shfl_xor_sync(0xffffffffu, sum1, 1);
            sum1 += __shfl_xor_sync(0xffffffffu, sum1, 2);
            l0[u] = l0[u] * al0 + sum0;
            l1[u] = l1[u] * al1 + sum1;
            #pragma unroll
            for (int nt = 0; nt < 8; nt++) {
                o[u][nt][0] *= al0; o[u][nt][1] *= al0;
                o[u][nt][2] *= al1; o[u][nt][3] *= al1;
            }
        }

        // O += P * V : P A-frag == S C-frag layout (same thread, just pack to half2)
        #pragma unroll
        for (int kk = 0; kk < 4; kk++) {
            unsigned b[8][2];
            #pragma unroll
            for (int p = 0; p < 4; p++)
                ldsm4(b[2*p][0], b[2*p][1], b[2*p+1][0], b[2*p+1][1],
                      Vts + swH(rB[p], kk*16 + eB));
            #pragma unroll
            for (int u = 0; u < 2; u++) {
                unsigned a[4];
                a[0] = packh2(s[u][2*kk][0],     s[u][2*kk][1]);
                a[1] = packh2(s[u][2*kk][2],     s[u][2*kk][3]);
                a[2] = packh2(s[u][2*kk + 1][0], s[u][2*kk + 1][1]);
                a[3] = packh2(s[u][2*kk + 1][2], s[u][2*kk + 1][3]);
                #pragma unroll
                for (int nt = 0; nt < 8; nt++) mma16h(o[u][nt], a, b[nt]);
            }
        }
    }

    // epilogue: normalize, write half2 pairs to g_attn[b, s, h*64+d]
    int bb = bh >> 4, h = bh & 15;
    #pragma unroll
    for (int u = 0; u < 2; u++) {
        float inv0 = 1.f / l0[u], inv1 = 1.f / l1[u];
        int q0 = qt*128 + wid*32 + u*16 + g;
        __half* base0 = g_attn + ((size_t)(bb*SEQ + q0) * EMBED) + h*64;
        __half* base1 = base0 + (size_t)8 * EMBED;
        #pragma unroll
        for (int nt = 0; nt < 8; nt++) {
            int d = nt*8 + 2*tg;
            *(__half2*)(base0 + d) = __floats2half2_rn(o[u][nt][0] * inv0, o[u][nt][1] * inv0);
            *(__half2*)(base1 + d) = __floats2half2_rn(o[u][nt][2] * inv1, o[u][nt][3] * inv1);
        }
    }
}

// ============ Kernel 3: output projection (fp32 out) ============
__global__ __launch_bounds__(128, 2) void oproj_kernel(float* __restrict__ out)
{
    extern __shared__ __align__(16) __half smem[];
    int row0 = blockIdx.y * 128, col0 = blockIdx.x * 128;
    float acc[4][8][4];
    gemm_core(g_attn, g_wo, row0, col0, smem, acc);

    int lane = threadIdx.x & 31, wid = threadIdx.x >> 5;
    int g = lane >> 2, tg = lane & 3, wm = wid >> 1, wn = wid & 1;
    #pragma unroll
    for (int mt = 0; mt < 4; mt++) {
        int r = row0 + wm*64 + mt*16 + g;
        #pragma unroll
        for (int nt = 0; nt < 8; nt++) {
            int c = col0 + wn*64 + nt*8 + 2*tg;
            float* p0 = out + (size_t)r * EMBED + c;
            float* p1 = out + (size_t)(r + 8) * EMBED + c;
            p0[0] = acc[mt][nt][0]; p0[1] = acc[mt][nt][1];
            p1[0] = acc[mt][nt][2]; p1[1] = acc[mt][nt][3];
        }
    }
}

// ============ launch ============
extern "C" void kernel_launch(void* const* d_in, const int* in_sizes, int n_in,
                              void* d_out, int out_size)
{
    const float* x  = (const float*)d_in[0];
    const float* Wq = (const float*)d_in[1];
    const float* Wk = (const float*)d_in[2];
    const float* Wv = (const float*)d_in[3];
    const float* Wo = (const float*)d_in[4];
    float* out = (float*)d_out;

    cudaFuncSetAttribute(qkv_kernel,   cudaFuncAttributeMaxDynamicSharedMemorySize, GEMM_SMEM_BYTES);
    cudaFuncSetAttribute(oproj_kernel, cudaFuncAttributeMaxDynamicSharedMemorySize, GEMM_SMEM_BYTES);
    cudaFuncSetAttribute(attn_kernel,  cudaFuncAttributeMaxDynamicSharedMemorySize, ATTN_SMEM_BYTES);

    __half* p_x;  cudaGetSymbolAddress((void**)&p_x,  g_x);
    __half* p_wq; cudaGetSymbolAddress((void**)&p_wq, g_wq);
    __half* p_wk; cudaGetSymbolAddress((void**)&p_wk, g_wk);
    __half* p_wv; cudaGetSymbolAddress((void**)&p_wv, g_wv);
    __half* p_wo; cudaGetSymbolAddress((void**)&p_wo, g_wo);

    int nx8 = MTOK*EMBED/8, nw8 = EMBED*EMBED/8;
    prep_kernel<<<(nx8 + 255)/256, 256>>>(x, p_x, nx8);
    prep_w_kernel<<<dim3(nw8/256, 1, 4), 256>>>(Wq, Wk, Wv, Wo, p_wq, p_wk, p_wv, p_wo);

    qkv_kernel<<<dim3(EMBED/128, MTOK/128, 3), 128, GEMM_SMEM_BYTES>>>();
    attn_kernel<<<dim3(SEQ/128, BATCH*NHEAD), 128, ATTN_SMEM_BYTES>>>();
    oproj_kernel<<<dim3(EMBED/128, MTOK/128), 128, GEMM_SMEM_BYTES>>>(out);
}

// round 16
// speedup vs baseline: 2.3841x; 1.0608x over previous
#include <cuda_runtime.h>
#include <cuda_fp16.h>
#include <math.h>

#define EMBED 1024
#define NHEAD 16
#define DK    64
#define BATCH 4
#define SEQ   2048
#define MTOK  (BATCH*SEQ)   // 8192
#define LOG2E 1.44269504f

// -------- scratch (device globals; no allocation allowed) --------
__device__ __half g_x [(size_t)MTOK*EMBED];
__device__ __half g_wq[(size_t)EMBED*EMBED];
__device__ __half g_wk[(size_t)EMBED*EMBED];
__device__ __half g_wv[(size_t)EMBED*EMBED];
__device__ __half g_wo[(size_t)EMBED*EMBED];
__device__ __half g_q[(size_t)BATCH*NHEAD*SEQ*DK];   // [b,h,s,d], pre-scaled by log2e/8
__device__ __half g_k[(size_t)BATCH*NHEAD*SEQ*DK];   // [b,h,s,d]
__device__ __half g_v[(size_t)BATCH*NHEAD*DK*SEQ];   // [b,h,d,s]  (TRANSPOSED)
__device__ __half g_attn[(size_t)MTOK*EMBED];

// -------- helpers --------
__device__ __forceinline__ float ex2(float x) {
    float r; asm("ex2.approx.f32 %0, %1;" : "=f"(r) : "f"(x)); return r;
}
__device__ __forceinline__ unsigned ex2h2(unsigned x) {
    unsigned r; asm("ex2.approx.f16x2 %0, %1;" : "=r"(r) : "r"(x)); return r;
}
__device__ __forceinline__ unsigned packh2(float a, float b) {
    __half2 h = __floats2half2_rn(a, b);
    return *(unsigned*)&h;
}

__device__ __forceinline__ void mma16h(float* c, const unsigned* a, const unsigned* b) {
    asm volatile("mma.sync.aligned.m16n8k16.row.col.f32.f16.f16.f32 "
        "{%0,%1,%2,%3},{%4,%5,%6,%7},{%8,%9},{%0,%1,%2,%3};"
        : "+f"(c[0]), "+f"(c[1]), "+f"(c[2]), "+f"(c[3])
        : "r"(a[0]), "r"(a[1]), "r"(a[2]), "r"(a[3]), "r"(b[0]), "r"(b[1]));
}

__device__ __forceinline__ void ldsm4(unsigned& r0, unsigned& r1, unsigned& r2, unsigned& r3,
                                      const void* p) {
    unsigned a = (unsigned)__cvta_generic_to_shared(p);
    asm volatile("ldmatrix.sync.aligned.m8n8.x4.shared.b16 {%0,%1,%2,%3},[%4];"
        : "=r"(r0), "=r"(r1), "=r"(r2), "=r"(r3) : "r"(a));
}

__device__ __forceinline__ void cpa16(void* dst, const void* src) {
    unsigned d = (unsigned)__cvta_generic_to_shared(dst);
    asm volatile("cp.async.ca.shared.global [%0], [%1], 16;" :: "r"(d), "l"(src));
}
#define CP_COMMIT() asm volatile("cp.async.commit_group;")
#define CP_WAIT(N)  asm volatile("cp.async.wait_group %0;" :: "n"(N))

// 128B-row swizzle for half tiles of row-width 64 halves (16B groups, full 8-XOR)
__device__ __forceinline__ int swH(int r, int c) {
    return r*64 + (((((c) >> 3) ^ (r & 7)) << 3) | (c & 7));
}

#define BKH    64                 // k-halves per GEMM tile
#define TBUFH  (128*64)           // halves per A (or B) tile = 16KB
#define STGH   (2*TBUFH)
#define NSTAGE 3
#define GEMM_SMEM_BYTES (NSTAGE * STGH * (int)sizeof(__half))   // 96KB

// ============ kernel 0: fp16 pre-conversion (8 elems/thread) ============
__global__ __launch_bounds__(256) void prep_kernel(const float* __restrict__ src,
                                                   __half* __restrict__ dst, int n8)
{
    int i = blockIdx.x * blockDim.x + threadIdx.x;
    if (i < n8) {
        float4 v0 = ((const float4*)src)[2*i];
        float4 v1 = ((const float4*)src)[2*i + 1];
        uint4 o;
        o.x = packh2(v0.x, v0.y); o.y = packh2(v0.z, v0.w);
        o.z = packh2(v1.x, v1.y); o.w = packh2(v1.z, v1.w);
        ((uint4*)dst)[i] = o;
    }
}

__global__ __launch_bounds__(256) void prep_w_kernel(
    const float* __restrict__ w0, const float* __restrict__ w1,
    const float* __restrict__ w2, const float* __restrict__ w3,
    __half* __restrict__ d0, __half* __restrict__ d1,
    __half* __restrict__ d2, __half* __restrict__ d3)
{
    int z = blockIdx.z;
    const float* src = (z == 0) ? w0 : (z == 1 ? w1 : (z == 2 ? w2 : w3));
    __half* dst      = (z == 0) ? d0 : (z == 1 ? d1 : (z == 2 ? d2 : d3));
    int i = blockIdx.x * blockDim.x + threadIdx.x;
    float4 v0 = ((const float4*)src)[2*i];
    float4 v1 = ((const float4*)src)[2*i + 1];
    uint4 o;
    o.x = packh2(v0.x, v0.y); o.y = packh2(v0.z, v0.w);
    o.z = packh2(v1.x, v1.y); o.w = packh2(v1.z, v1.w);
    ((uint4*)dst)[i] = o;
}

// ============ 128x128 NT GEMM core (fp16, K=1024), cp.async 3-stage ============
// 128 threads = 4 warps (2m x 2n); warp tile 64x64; mma m16n8k16.
__device__ __forceinline__ void gemm_core(
    const __half* __restrict__ A, const __half* __restrict__ W,
    int row0, int col0, __half* smem, float acc[4][8][4])
{
    const int K = EMBED;
    int tid  = threadIdx.x;
    int lane = tid & 31, wid = tid >> 5;
    int wm = wid >> 1, wn = wid & 1;

    #pragma unroll
    for (int mt = 0; mt < 4; mt++)
        #pragma unroll
        for (int nt = 0; nt < 8; nt++)
            #pragma unroll
            for (int i = 0; i < 4; i++) acc[mt][nt][i] = 0.f;

    int fr[8], fcH[8];
    #pragma unroll
    for (int i = 0; i < 8; i++) { int f = tid + 128*i; fr[i] = f >> 3; fcH[i] = (f & 7) * 8; }

    int offA[4][4], offB[4][4];
    {
        int eA = ((lane >> 4) & 1) * 8;
        int eB = ((lane >> 3) & 1) * 8;
        #pragma unroll
        for (int mt = 0; mt < 4; mt++) {
            int r = wm*64 + mt*16 + (lane & 15);
            #pragma unroll
            for (int s = 0; s < 4; s++) offA[mt][s] = swH(r, s*16 + eA);
        }
        #pragma unroll
        for (int p = 0; p < 4; p++) {
            int r = wn*64 + p*16 + (lane & 7) + ((lane >> 4) & 1) * 8;
            #pragma unroll
            for (int s = 0; s < 4; s++) offB[p][s] = swH(r, s*16 + eB);
        }
    }

    const __half* Abase = A + (size_t)row0 * K;
    const __half* Bbase = W + (size_t)col0 * K;

    auto issue = [&](int kt) {
        __half* st = smem + (kt % NSTAGE) * STGH;
        const __half* Ab = Abase + kt * BKH;
        const __half* Bb = Bbase + kt * BKH;
        #pragma unroll
        for (int i = 0; i < 8; i++)
            cpa16(st + swH(fr[i], fcH[i]), Ab + (size_t)fr[i] * K + fcH[i]);
        #pragma unroll
        for (int i = 0; i < 8; i++)
            cpa16(st + TBUFH + swH(fr[i], fcH[i]), Bb + (size_t)fr[i] * K + fcH[i]);
        CP_COMMIT();
    };

    const int NK = K / BKH;   // 16
    issue(0); issue(1);
    for (int kt = 0; kt < NK; kt++) {
        if (kt + 1 < NK) { CP_WAIT(1); } else { CP_WAIT(0); }
        __syncthreads();
        if (kt + 2 < NK) issue(kt + 2);
        const __half* Ab = smem + (kt % NSTAGE) * STGH;
        const __half* Bb = Ab + TBUFH;
        #pragma unroll
        for (int s = 0; s < 4; s++) {
            unsigned a[4][4], b[8][2];
            #pragma unroll
            for (int mt = 0; mt < 4; mt++)
                ldsm4(a[mt][0], a[mt][1], a[mt][2], a[mt][3], Ab + offA[mt][s]);
            #pragma unroll
            for (int p = 0; p < 4; p++)
                ldsm4(b[2*p][0], b[2*p][1], b[2*p+1][0], b[2*p+1][1], Bb + offB[p][s]);
            #pragma unroll
            for (int mt = 0; mt < 4; mt++)
                #pragma unroll
                for (int nt = 0; nt < 8; nt++)
                    mma16h(acc[mt][nt], a[mt], b[nt]);
        }
    }
}

// ============ Kernel 1: fused QKV projections (grid.z picks Q/K/V) ============
__global__ __launch_bounds__(128, 2) void qkv_kernel()
{
    extern __shared__ __align__(16) __half smem[];
    int row0 = blockIdx.y * 128, col0 = blockIdx.x * 128;
    int z = blockIdx.z;
    const __half* W = (z == 0) ? g_wq : (z == 1 ? g_wk : g_wv);
    float scale     = (z == 0) ? 0.125f * LOG2E : 1.0f;

    float acc[4][8][4];
    gemm_core(g_x, W, row0, col0, smem, acc);

    int lane = threadIdx.x & 31, wid = threadIdx.x >> 5;
    int g = lane >> 2, tg = lane & 3, wm = wid >> 1, wn = wid & 1;
    #pragma unroll
    for (int mt = 0; mt < 4; mt++) {
        int r = row0 + wm*64 + mt*16 + g;
        int bb = r >> 11, ss = r & 2047;
        #pragma unroll
        for (int nt = 0; nt < 8; nt++) {
            int c = col0 + wn*64 + nt*8 + 2*tg;
            int h = c >> 6, d = c & 63;
            if (z == 2) {
                __half* pv = g_v + (((size_t)(bb*NHEAD + h) * DK + d) * SEQ + ss);
                pv[0]       = __float2half_rn(acc[mt][nt][0]);
                pv[SEQ]     = __float2half_rn(acc[mt][nt][1]);
                pv[8]       = __float2half_rn(acc[mt][nt][2]);
                pv[SEQ + 8] = __float2half_rn(acc[mt][nt][3]);
            } else {
                __half* dst = (z == 0) ? g_q : g_k;
                __half* p0 = dst + (((size_t)(bb*NHEAD + h) * SEQ + ss) * DK + d);
                __half* p1 = p0 + 8*DK;
                *(__half2*)p0 = __floats2half2_rn(acc[mt][nt][0] * scale, acc[mt][nt][1] * scale);
                *(__half2*)p1 = __floats2half2_rn(acc[mt][nt][2] * scale, acc[mt][nt][3] * scale);
            }
        }
    }
}

// ============ Kernel 2: flash attention (fp16), 128q CTA, 32q/warp ============
// P stays in registers; ex2 on f16x2 pairs; row-sums l via MMA with all-ones B.
#define ATTN_SMEM_BYTES ((8192 + 2*8192) * (int)sizeof(__half))
__global__ __launch_bounds__(128, 2) void attn_kernel()
{
    extern __shared__ __align__(16) __half asm_[];
    __half* Qs = asm_;               // 128 x 64 halves
    __half* KV = asm_ + 8192;        // stage s at s*8192: K 4096H, V 4096H

    int qt = blockIdx.x, bh = blockIdx.y;
    const __half* Qp = g_q + (size_t)bh * SEQ * DK + (size_t)qt * 128 * DK;
    const __half* Kp = g_k + (size_t)bh * SEQ * DK;
    const __half* Vp = g_v + (size_t)bh * DK * SEQ;   // [d, s]

    int tid = threadIdx.x, lane = tid & 31, wid = tid >> 5;
    int g = lane >> 2, tg = lane & 3;

    int eA = ((lane >> 4) & 1) * 8;
    int rA0 = wid*32 + (lane & 15);
    int eB = ((lane >> 3) & 1) * 8;
    int rB[4];
    #pragma unroll
    for (int p = 0; p < 4; p++) rB[p] = p*16 + (lane & 7) + ((lane >> 4) & 1) * 8;

    const unsigned ones_b[2] = {0x3C003C00u, 0x3C003C00u};   // half2(1,1) x2

    int adKV[4], goffK[4], goffV[4];
    #pragma unroll
    for (int i = 0; i < 4; i++) {
        int f = tid + 128*i;
        int r = f >> 3, c8 = (f & 7) * 8;
        adKV[i]  = swH(r, c8);
        goffK[i] = r*64 + c8;
        goffV[i] = r*SEQ + c8;
    }

    #pragma unroll
    for (int i = 0; i < 8; i++) {
        int f = tid + 128*i;
        int r = f >> 3, c8 = (f & 7) * 8;
        cpa16(Qs + swH(r, c8), Qp + r*64 + c8);
    }
    CP_COMMIT();
    #pragma unroll
    for (int i = 0; i < 4; i++) {
        cpa16(KV + adKV[i],        Kp + goffK[i]);
        cpa16(KV + 4096 + adKV[i], Vp + goffV[i]);
    }
    CP_COMMIT();

    unsigned qf[2][4][4];
    CP_WAIT(1);
    __syncthreads();
    #pragma unroll
    for (int u = 0; u < 2; u++)
        #pragma unroll
        for (int ks = 0; ks < 4; ks++)
            ldsm4(qf[u][ks][0], qf[u][ks][1], qf[u][ks][2], qf[u][ks][3],
                  Qs + swH(rA0 + u*16, ks*16 + eA));

    float o[2][8][4], lac[2][4];
    #pragma unroll
    for (int u = 0; u < 2; u++) {
        #pragma unroll
        for (int nt = 0; nt < 8; nt++)
            #pragma unroll
            for (int i = 0; i < 4; i++) o[u][nt][i] = 0.f;
        #pragma unroll
        for (int i = 0; i < 4; i++) lac[u][i] = 0.f;
    }
    float m0[2] = {-1e30f, -1e30f}, m1[2] = {-1e30f, -1e30f};

    const int NT = SEQ/64;
    for (int kt = 0; kt < NT; kt++) {
        CP_WAIT(0);
        __syncthreads();

        if (kt + 1 < NT) {
            __half* st = KV + ((kt + 1) & 1) * 8192;
            int t = (kt + 1) * 64;
            #pragma unroll
            for (int i = 0; i < 4; i++) {
                cpa16(st + adKV[i],        Kp + (size_t)t * DK + goffK[i]);
                cpa16(st + 4096 + adKV[i], Vp + t + goffV[i]);
            }
            CP_COMMIT();
        }

        const __half* Ks  = KV + (kt & 1) * 8192;
        const __half* Vts = Ks + 4096;

        // S = Q * K^T  (logits pre-scaled by log2e/8)
        float s[2][8][4];
        #pragma unroll
        for (int u = 0; u < 2; u++)
            #pragma unroll
            for (int nt = 0; nt < 8; nt++)
                #pragma unroll
                for (int i = 0; i < 4; i++) s[u][nt][i] = 0.f;
        #pragma unroll
        for (int ks = 0; ks < 4; ks++) {
            unsigned b[8][2];
            #pragma unroll
            for (int p = 0; p < 4; p++)
                ldsm4(b[2*p][0], b[2*p][1], b[2*p+1][0], b[2*p+1][1],
                      Ks + swH(rB[p], ks*16 + eB));
            #pragma unroll
            for (int nt = 0; nt < 8; nt++) mma16h(s[0][nt], qf[0][ks], b[nt]);
            #pragma unroll
            for (int nt = 0; nt < 8; nt++) mma16h(s[1][nt], qf[1][ks], b[nt]);
        }

        // softmax: max-reduce, rescale o & l, build P fragments (ex2.f16x2)
        unsigned pf[2][16];
        #pragma unroll
        for (int u = 0; u < 2; u++) {
            float ml0 = -1e30f, ml1 = -1e30f;
            #pragma unroll
            for (int nt = 0; nt < 8; nt++) {
                ml0 = fmaxf(ml0, fmaxf(s[u][nt][0], s[u][nt][1]));
                ml1 = fmaxf(ml1, fmaxf(s[u][nt][2], s[u][nt][3]));
            }
            ml0 = fmaxf(ml0, __shfl_xor_sync(0xffffffffu, ml0, 1));
            ml0 = fmaxf(ml0, __shfl_xor_sync(0xffffffffu, ml0, 2));
            ml1 = fmaxf(ml1, __shfl_xor_sync(0xffffffffu, ml1, 1));
            ml1 = fmaxf(ml1, __shfl_xor_sync(0xffffffffu, ml1, 2));
            float mn0 = fmaxf(m0[u], ml0), mn1 = fmaxf(m1[u], ml1);
            float al0 = ex2(m0[u] - mn0), al1 = ex2(m1[u] - mn1);
            m0[u] = mn0; m1[u] = mn1;
            #pragma unroll
            for (int nt = 0; nt < 8; nt++) {
                pf[u][2*nt]     = ex2h2(packh2(s[u][nt][0] - mn0, s[u][nt][1] - mn0));
                pf[u][2*nt + 1] = ex2h2(packh2(s[u][nt][2] - mn1, s[u][nt][3] - mn1));
            }
            #pragma unroll
            for (int nt = 0; nt < 8; nt++) {
                o[u][nt][0] *= al0; o[u][nt][1] *= al0;
                o[u][nt][2] *= al1; o[u][nt][3] *= al1;
            }
            lac[u][0] *= al0; lac[u][1] *= al0;
            lac[u][2] *= al1; lac[u][3] *= al1;
        }

        // O += P * V ; l += P * 1 (ones-B mma, no ldsm)
        #pragma unroll
        for (int kk = 0; kk < 4; kk++) {
            unsigned b[8][2];
            #pragma unroll
            for (int p = 0; p < 4; p++)
                ldsm4(b[2*p][0], b[2*p][1], b[2*p+1][0], b[2*p+1][1],
                      Vts + swH(rB[p], kk*16 + eB));
            #pragma unroll
            for (int u = 0; u < 2; u++) {
                const unsigned* a = &pf[u][4*kk];
                #pragma unroll
                for (int nt = 0; nt < 8; nt++) mma16h(o[u][nt], a, b[nt]);
                mma16h(lac[u], a, ones_b);
            }
        }
    }

    // epilogue: normalize (l from the ones-mma C-fragment), write half2 pairs
    int bb = bh >> 4, h = bh & 15;
    #pragma unroll
    for (int u = 0; u < 2; u++) {
        float inv0 = 1.f / lac[u][0], inv1 = 1.f / lac[u][2];
        int q0 = qt*128 + wid*32 + u*16 + g;
        __half* base0 = g_attn + ((size_t)(bb*SEQ + q0) * EMBED) + h*64;
        __half* base1 = base0 + (size_t)8 * EMBED;
        #pragma unroll
        for (int nt = 0; nt < 8; nt++) {
            int d = nt*8 + 2*tg;
            *(__half2*)(base0 + d) = __floats2half2_rn(o[u][nt][0] * inv0, o[u][nt][1] * inv0);
            *(__half2*)(base1 + d) = __floats2half2_rn(o[u][nt][2] * inv1, o[u][nt][3] * inv1);
        }
    }
}

// ============ Kernel 3: output projection (fp32 out) ============
__global__ __launch_bounds__(128, 2) void oproj_kernel(float* __restrict__ out)
{
    extern __shared__ __align__(16) __half smem[];
    int row0 = blockIdx.y * 128, col0 = blockIdx.x * 128;
    float acc[4][8][4];
    gemm_core(g_attn, g_wo, row0, col0, smem, acc);

    int lane = threadIdx.x & 31, wid = threadIdx.x >> 5;
    int g = lane >> 2, tg = lane & 3, wm = wid >> 1, wn = wid & 1;
    #pragma unroll
    for (int mt = 0; mt < 4; mt++) {
        int r = row0 + wm*64 + mt*16 + g;
        #pragma unroll
        for (int nt = 0; nt < 8; nt++) {
            int c = col0 + wn*64 + nt*8 + 2*tg;
            float* p0 = out + (size_t)r * EMBED + c;
            float* p1 = out + (size_t)(r + 8) * EMBED + c;
            p0[0] = acc[mt][nt][0]; p0[1] = acc[mt][nt][1];
            p1[0] = acc[mt][nt][2]; p1[1] = acc[mt][nt][3];
        }
    }
}

// ============ launch ============
extern "C" void kernel_launch(void* const* d_in, const int* in_sizes, int n_in,
                              void* d_out, int out_size)
{
    const float* x  = (const float*)d_in[0];
    const float* Wq = (const float*)d_in[1];
    const float* Wk = (const float*)d_in[2];
    const float* Wv = (const float*)d_in[3];
    const float* Wo = (const float*)d_in[4];
    float* out = (float*)d_out;

    cudaFuncSetAttribute(qkv_kernel,   cudaFuncAttributeMaxDynamicSharedMemorySize, GEMM_SMEM_BYTES);
    cudaFuncSetAttribute(oproj_kernel, cudaFuncAttributeMaxDynamicSharedMemorySize, GEMM_SMEM_BYTES);
    cudaFuncSetAttribute(attn_kernel,  cudaFuncAttributeMaxDynamicSharedMemorySize, ATTN_SMEM_BYTES);

    __half* p_x;  cudaGetSymbolAddress((void**)&p_x,  g_x);
    __half* p_wq; cudaGetSymbolAddress((void**)&p_wq, g_wq);
    __half* p_wk; cudaGetSymbolAddress((void**)&p_wk, g_wk);
    __half* p_wv; cudaGetSymbolAddress((void**)&p_wv, g_wv);
    __half* p_wo; cudaGetSymbolAddress((void**)&p_wo, g_wo);

    int nx8 = MTOK*EMBED/8, nw8 = EMBED*EMBED/8;
    prep_kernel<<<(nx8 + 255)/256, 256>>>(x, p_x, nx8);
    prep_w_kernel<<<dim3(nw8/256, 1, 4), 256>>>(Wq, Wk, Wv, Wo, p_wq, p_wk, p_wv, p_wo);

    qkv_kernel<<<dim3(EMBED/128, MTOK/128, 3), 128, GEMM_SMEM_BYTES>>>();
    attn_kernel<<<dim3(SEQ/128, BATCH*NHEAD), 128, ATTN_SMEM_BYTES>>>();
    oproj_kernel<<<dim3(EMBED/128, MTOK/128), 128, GEMM_SMEM_BYTES>>>(out);
}

// round 17
// speedup vs baseline: 2.4837x; 1.0418x over previous
#include <cuda_runtime.h>
#include <cuda_fp16.h>
#include <math.h>

#define EMBED 1024
#define NHEAD 16
#define DK    64
#define BATCH 4
#define SEQ   2048
#define MTOK  (BATCH*SEQ)   // 8192
#define LOG2E 1.44269504f

// -------- scratch (device globals; no allocation allowed) --------
__device__ __half g_x [(size_t)MTOK*EMBED];
__device__ __half g_wq[(size_t)EMBED*EMBED];
__device__ __half g_wk[(size_t)EMBED*EMBED];
__device__ __half g_wv[(size_t)EMBED*EMBED];
__device__ __half g_wo[(size_t)EMBED*EMBED];
__device__ __half g_q[(size_t)BATCH*NHEAD*SEQ*DK];   // [b,h,s,d], pre-scaled by log2e/8
__device__ __half g_k[(size_t)BATCH*NHEAD*SEQ*DK];   // [b,h,s,d]
__device__ __half g_v[(size_t)BATCH*NHEAD*DK*SEQ];   // [b,h,d,s]  (TRANSPOSED)
__device__ __half g_attn[(size_t)MTOK*EMBED];

// -------- helpers --------
__device__ __forceinline__ float ex2(float x) {
    float r; asm("ex2.approx.f32 %0, %1;" : "=f"(r) : "f"(x)); return r;
}
__device__ __forceinline__ unsigned ex2h2(unsigned x) {
    unsigned r; asm("ex2.approx.f16x2 %0, %1;" : "=r"(r) : "r"(x)); return r;
}
__device__ __forceinline__ unsigned packh2(float a, float b) {
    __half2 h = __floats2half2_rn(a, b);
    return *(unsigned*)&h;
}

__device__ __forceinline__ void mma16h(float* c, const unsigned* a, const unsigned* b) {
    asm volatile("mma.sync.aligned.m16n8k16.row.col.f32.f16.f16.f32 "
        "{%0,%1,%2,%3},{%4,%5,%6,%7},{%8,%9},{%0,%1,%2,%3};"
        : "+f"(c[0]), "+f"(c[1]), "+f"(c[2]), "+f"(c[3])
        : "r"(a[0]), "r"(a[1]), "r"(a[2]), "r"(a[3]), "r"(b[0]), "r"(b[1]));
}

__device__ __forceinline__ void ldsm4(unsigned& r0, unsigned& r1, unsigned& r2, unsigned& r3,
                                      const void* p) {
    unsigned a = (unsigned)__cvta_generic_to_shared(p);
    asm volatile("ldmatrix.sync.aligned.m8n8.x4.shared.b16 {%0,%1,%2,%3},[%4];"
        : "=r"(r0), "=r"(r1), "=r"(r2), "=r"(r3) : "r"(a));
}

__device__ __forceinline__ void cpa16(void* dst, const void* src) {
    unsigned d = (unsigned)__cvta_generic_to_shared(dst);
    asm volatile("cp.async.ca.shared.global [%0], [%1], 16;" :: "r"(d), "l"(src));
}
#define CP_COMMIT() asm volatile("cp.async.commit_group;")
#define CP_WAIT(N)  asm volatile("cp.async.wait_group %0;" :: "n"(N))

// 128B-row swizzle for half tiles of row-width 64 halves (16B groups, full 8-XOR)
__device__ __forceinline__ int swH(int r, int c) {
    return r*64 + (((((c) >> 3) ^ (r & 7)) << 3) | (c & 7));
}

#define BKH    64                 // k-halves per GEMM tile
#define TBUFH  (128*64)           // halves per A (or B) tile = 16KB
#define STGH   (2*TBUFH)
#define NSTAGE 3
#define GEMM_SMEM_BYTES (NSTAGE * STGH * (int)sizeof(__half))   // 96KB
#define EPI_STRIDE 136            // halves; bank-conflict-free bounce stride

// ============ kernel 0: fp16 pre-conversion (8 elems/thread) ============
__global__ __launch_bounds__(256) void prep_kernel(const float* __restrict__ src,
                                                   __half* __restrict__ dst, int n8)
{
    int i = blockIdx.x * blockDim.x + threadIdx.x;
    if (i < n8) {
        float4 v0 = ((const float4*)src)[2*i];
        float4 v1 = ((const float4*)src)[2*i + 1];
        uint4 o;
        o.x = packh2(v0.x, v0.y); o.y = packh2(v0.z, v0.w);
        o.z = packh2(v1.x, v1.y); o.w = packh2(v1.z, v1.w);
        ((uint4*)dst)[i] = o;
    }
}

__global__ __launch_bounds__(256) void prep_w_kernel(
    const float* __restrict__ w0, const float* __restrict__ w1,
    const float* __restrict__ w2, const float* __restrict__ w3,
    __half* __restrict__ d0, __half* __restrict__ d1,
    __half* __restrict__ d2, __half* __restrict__ d3)
{
    int z = blockIdx.z;
    const float* src = (z == 0) ? w0 : (z == 1 ? w1 : (z == 2 ? w2 : w3));
    __half* dst      = (z == 0) ? d0 : (z == 1 ? d1 : (z == 2 ? d2 : d3));
    int i = blockIdx.x * blockDim.x + threadIdx.x;
    float4 v0 = ((const float4*)src)[2*i];
    float4 v1 = ((const float4*)src)[2*i + 1];
    uint4 o;
    o.x = packh2(v0.x, v0.y); o.y = packh2(v0.z, v0.w);
    o.z = packh2(v1.x, v1.y); o.w = packh2(v1.z, v1.w);
    ((uint4*)dst)[i] = o;
}

// ============ 128x128 NT GEMM core (fp16, K=1024), cp.async 3-stage ============
// 128 threads = 4 warps (2m x 2n); warp tile 64x64; mma m16n8k16.
__device__ __forceinline__ void gemm_core(
    const __half* __restrict__ A, const __half* __restrict__ W,
    int row0, int col0, __half* smem, float acc[4][8][4])
{
    const int K = EMBED;
    int tid  = threadIdx.x;
    int lane = tid & 31, wid = tid >> 5;
    int wm = wid >> 1, wn = wid & 1;

    #pragma unroll
    for (int mt = 0; mt < 4; mt++)
        #pragma unroll
        for (int nt = 0; nt < 8; nt++)
            #pragma unroll
            for (int i = 0; i < 4; i++) acc[mt][nt][i] = 0.f;

    int fr[8], fcH[8];
    #pragma unroll
    for (int i = 0; i < 8; i++) { int f = tid + 128*i; fr[i] = f >> 3; fcH[i] = (f & 7) * 8; }

    int offA[4][4], offB[4][4];
    {
        int eA = ((lane >> 4) & 1) * 8;
        int eB = ((lane >> 3) & 1) * 8;
        #pragma unroll
        for (int mt = 0; mt < 4; mt++) {
            int r = wm*64 + mt*16 + (lane & 15);
            #pragma unroll
            for (int s = 0; s < 4; s++) offA[mt][s] = swH(r, s*16 + eA);
        }
        #pragma unroll
        for (int p = 0; p < 4; p++) {
            int r = wn*64 + p*16 + (lane & 7) + ((lane >> 4) & 1) * 8;
            #pragma unroll
            for (int s = 0; s < 4; s++) offB[p][s] = swH(r, s*16 + eB);
        }
    }

    const __half* Abase = A + (size_t)row0 * K;
    const __half* Bbase = W + (size_t)col0 * K;

    auto issue = [&](int kt) {
        __half* st = smem + (kt % NSTAGE) * STGH;
        const __half* Ab = Abase + kt * BKH;
        const __half* Bb = Bbase + kt * BKH;
        #pragma unroll
        for (int i = 0; i < 8; i++)
            cpa16(st + swH(fr[i], fcH[i]), Ab + (size_t)fr[i] * K + fcH[i]);
        #pragma unroll
        for (int i = 0; i < 8; i++)
            cpa16(st + TBUFH + swH(fr[i], fcH[i]), Bb + (size_t)fr[i] * K + fcH[i]);
        CP_COMMIT();
    };

    const int NK = K / BKH;   // 16
    issue(0); issue(1);
    for (int kt = 0; kt < NK; kt++) {
        if (kt + 1 < NK) { CP_WAIT(1); } else { CP_WAIT(0); }
        __syncthreads();
        if (kt + 2 < NK) issue(kt + 2);
        const __half* Ab = smem + (kt % NSTAGE) * STGH;
        const __half* Bb = Ab + TBUFH;
        #pragma unroll
        for (int s = 0; s < 4; s++) {
            unsigned a[4][4], b[8][2];
            #pragma unroll
            for (int mt = 0; mt < 4; mt++)
                ldsm4(a[mt][0], a[mt][1], a[mt][2], a[mt][3], Ab + offA[mt][s]);
            #pragma unroll
            for (int p = 0; p < 4; p++)
                ldsm4(b[2*p][0], b[2*p][1], b[2*p+1][0], b[2*p+1][1], Bb + offB[p][s]);
            #pragma unroll
            for (int mt = 0; mt < 4; mt++)
                #pragma unroll
                for (int nt = 0; nt < 8; nt++)
                    mma16h(acc[mt][nt], a[mt], b[nt]);
        }
    }
}

// ============ Kernel 1: fused QKV projections (grid.z picks Q/K/V) ============
// Coalesced epilogues via smem bounce. V written TRANSPOSED to g_v[b,h,d,s].
__global__ __launch_bounds__(128, 2) void qkv_kernel()
{
    extern __shared__ __align__(16) __half smem[];
    int row0 = blockIdx.y * 128, col0 = blockIdx.x * 128;
    int z = blockIdx.z;
    const __half* W = (z == 0) ? g_wq : (z == 1 ? g_wk : g_wv);
    float scale     = (z == 0) ? 0.125f * LOG2E : 1.0f;

    float acc[4][8][4];
    gemm_core(g_x, W, row0, col0, smem, acc);

    int tid = threadIdx.x, lane = tid & 31, wid = tid >> 5;
    int g = lane >> 2, tg = lane & 3, wm = wid >> 1, wn = wid & 1;
    int bb = row0 >> 11, ss0 = row0 & 2047, h0 = col0 >> 6;

    __syncthreads();   // mainloop smem now dead; reuse as bounce buffer

    if (z == 2) {
        // transpose in smem: tile_t[c][r], stride EPI_STRIDE
        #pragma unroll
        for (int mt = 0; mt < 4; mt++) {
            int r = wm*64 + mt*16 + g;
            #pragma unroll
            for (int nt = 0; nt < 8; nt++) {
                int c = wn*64 + nt*8 + 2*tg;
                smem[(c    )*EPI_STRIDE + r    ] = __float2half_rn(acc[mt][nt][0]);
                smem[(c + 1)*EPI_STRIDE + r    ] = __float2half_rn(acc[mt][nt][1]);
                smem[(c    )*EPI_STRIDE + r + 8] = __float2half_rn(acc[mt][nt][2]);
                smem[(c + 1)*EPI_STRIDE + r + 8] = __float2half_rn(acc[mt][nt][3]);
            }
        }
        __syncthreads();
        // write g_v rows: feature c -> 128 contiguous tokens (16 uint4)
        #pragma unroll
        for (int i = 0; i < 16; i++) {
            int idx = tid + 128*i;        // 128 c x 16 chunks
            int c = idx >> 4, k8 = (idx & 15) * 8;
            uint4 v = *(uint4*)(smem + c*EPI_STRIDE + k8);
            int h = h0 + (c >> 6), d = c & 63;
            *(uint4*)(g_v + (((size_t)(bb*NHEAD + h) * DK + d) * SEQ + ss0 + k8)) = v;
        }
    } else {
        __half* dst = (z == 0) ? g_q : g_k;
        #pragma unroll
        for (int mt = 0; mt < 4; mt++) {
            int r = wm*64 + mt*16 + g;
            #pragma unroll
            for (int nt = 0; nt < 8; nt++) {
                int c = wn*64 + nt*8 + 2*tg;
                *(__half2*)(smem + r*EPI_STRIDE + c) =
                    __floats2half2_rn(acc[mt][nt][0] * scale, acc[mt][nt][1] * scale);
                *(__half2*)(smem + (r + 8)*EPI_STRIDE + c) =
                    __floats2half2_rn(acc[mt][nt][2] * scale, acc[mt][nt][3] * scale);
            }
        }
        __syncthreads();
        // write rows: (token r, head hh) -> 64 contiguous d (8 uint4)
        #pragma unroll
        for (int i = 0; i < 16; i++) {
            int idx = tid + 128*i;        // 128 r x 2 hh x 8 chunks
            int r = idx >> 4, hh = (idx >> 3) & 1, k8 = (idx & 7) * 8;
            uint4 v = *(uint4*)(smem + r*EPI_STRIDE + hh*64 + k8);
            *(uint4*)(dst + (((size_t)(bb*NHEAD + h0 + hh) * SEQ + ss0 + r) * DK + k8)) = v;
        }
    }
}

// ============ Kernel 2: flash attention (fp16), 128q CTA, 32q/warp ============
// P stays in registers; ex2 on f16x2 pairs; row-sums l via MMA with all-ones B.
#define ATTN_SMEM_BYTES ((8192 + 2*8192) * (int)sizeof(__half))
__global__ __launch_bounds__(128, 2) void attn_kernel()
{
    extern __shared__ __align__(16) __half asm_[];
    __half* Qs = asm_;               // 128 x 64 halves
    __half* KV = asm_ + 8192;        // stage s at s*8192: K 4096H, V 4096H

    int qt = blockIdx.x, bh = blockIdx.y;
    const __half* Qp = g_q + (size_t)bh * SEQ * DK + (size_t)qt * 128 * DK;
    const __half* Kp = g_k + (size_t)bh * SEQ * DK;
    const __half* Vp = g_v + (size_t)bh * DK * SEQ;   // [d, s]

    int tid = threadIdx.x, lane = tid & 31, wid = tid >> 5;
    int g = lane >> 2, tg = lane & 3;

    int eA = ((lane >> 4) & 1) * 8;
    int rA0 = wid*32 + (lane & 15);
    int eB = ((lane >> 3) & 1) * 8;
    int rB[4];
    #pragma unroll
    for (int p = 0; p < 4; p++) rB[p] = p*16 + (lane & 7) + ((lane >> 4) & 1) * 8;

    const unsigned ones_b[2] = {0x3C003C00u, 0x3C003C00u};   // half2(1,1) x2

    int adKV[4], goffK[4], goffV[4];
    #pragma unroll
    for (int i = 0; i < 4; i++) {
        int f = tid + 128*i;
        int r = f >> 3, c8 = (f & 7) * 8;
        adKV[i]  = swH(r, c8);
        goffK[i] = r*64 + c8;
        goffV[i] = r*SEQ + c8;
    }

    #pragma unroll
    for (int i = 0; i < 8; i++) {
        int f = tid + 128*i;
        int r = f >> 3, c8 = (f & 7) * 8;
        cpa16(Qs + swH(r, c8), Qp + r*64 + c8);
    }
    CP_COMMIT();
    #pragma unroll
    for (int i = 0; i < 4; i++) {
        cpa16(KV + adKV[i],        Kp + goffK[i]);
        cpa16(KV + 4096 + adKV[i], Vp + goffV[i]);
    }
    CP_COMMIT();

    unsigned qf[2][4][4];
    CP_WAIT(1);
    __syncthreads();
    #pragma unroll
    for (int u = 0; u < 2; u++)
        #pragma unroll
        for (int ks = 0; ks < 4; ks++)
            ldsm4(qf[u][ks][0], qf[u][ks][1], qf[u][ks][2], qf[u][ks][3],
                  Qs + swH(rA0 + u*16, ks*16 + eA));

    float o[2][8][4], lac[2][4];
    #pragma unroll
    for (int u = 0; u < 2; u++) {
        #pragma unroll
        for (int nt = 0; nt < 8; nt++)
            #pragma unroll
            for (int i = 0; i < 4; i++) o[u][nt][i] = 0.f;
        #pragma unroll
        for (int i = 0; i < 4; i++) lac[u][i] = 0.f;
    }
    float m0[2] = {-1e30f, -1e30f}, m1[2] = {-1e30f, -1e30f};

    const int NT = SEQ/64;
    for (int kt = 0; kt < NT; kt++) {
        CP_WAIT(0);
        __syncthreads();

        if (kt + 1 < NT) {
            __half* st = KV + ((kt + 1) & 1) * 8192;
            int t = (kt + 1) * 64;
            #pragma unroll
            for (int i = 0; i < 4; i++) {
                cpa16(st + adKV[i],        Kp + (size_t)t * DK + goffK[i]);
                cpa16(st + 4096 + adKV[i], Vp + t + goffV[i]);
            }
            CP_COMMIT();
        }

        const __half* Ks  = KV + (kt & 1) * 8192;
        const __half* Vts = Ks + 4096;

        // S = Q * K^T  (logits pre-scaled by log2e/8)
        float s[2][8][4];
        #pragma unroll
        for (int u = 0; u < 2; u++)
            #pragma unroll
            for (int nt = 0; nt < 8; nt++)
                #pragma unroll
                for (int i = 0; i < 4; i++) s[u][nt][i] = 0.f;
        #pragma unroll
        for (int ks = 0; ks < 4; ks++) {
            unsigned b[8][2];
            #pragma unroll
            for (int p = 0; p < 4; p++)
                ldsm4(b[2*p][0], b[2*p][1], b[2*p+1][0], b[2*p+1][1],
                      Ks + swH(rB[p], ks*16 + eB));
            #pragma unroll
            for (int nt = 0; nt < 8; nt++) mma16h(s[0][nt], qf[0][ks], b[nt]);
            #pragma unroll
            for (int nt = 0; nt < 8; nt++) mma16h(s[1][nt], qf[1][ks], b[nt]);
        }

        // softmax: max-reduce, rescale o & l, build P fragments (ex2.f16x2)
        unsigned pf[2][16];
        #pragma unroll
        for (int u = 0; u < 2; u++) {
            float ml0 = -1e30f, ml1 = -1e30f;
            #pragma unroll
            for (int nt = 0; nt < 8; nt++) {
                ml0 = fmaxf(ml0, fmaxf(s[u][nt][0], s[u][nt][1]));
                ml1 = fmaxf(ml1, fmaxf(s[u][nt][2], s[u][nt][3]));
            }
            ml0 = fmaxf(ml0, __shfl_xor_sync(0xffffffffu, ml0, 1));
            ml0 = fmaxf(ml0, __shfl_xor_sync(0xffffffffu, ml0, 2));
            ml1 = fmaxf(ml1, __shfl_xor_sync(0xffffffffu, ml1, 1));
            ml1 = fmaxf(ml1, __shfl_xor_sync(0xffffffffu, ml1, 2));
            float mn0 = fmaxf(m0[u], ml0), mn1 = fmaxf(m1[u], ml1);
            float al0 = ex2(m0[u] - mn0), al1 = ex2(m1[u] - mn1);
            m0[u] = mn0; m1[u] = mn1;
            #pragma unroll
            for (int nt = 0; nt < 8; nt++) {
                pf[u][2*nt]     = ex2h2(packh2(s[u][nt][0] - mn0, s[u][nt][1] - mn0));
                pf[u][2*nt + 1] = ex2h2(packh2(s[u][nt][2] - mn1, s[u][nt][3] - mn1));
            }
            #pragma unroll
            for (int nt = 0; nt < 8; nt++) {
                o[u][nt][0] *= al0; o[u][nt][1] *= al0;
                o[u][nt][2] *= al1; o[u][nt][3] *= al1;
            }
            lac[u][0] *= al0; lac[u][1] *= al0;
            lac[u][2] *= al1; lac[u][3] *= al1;
        }

        // O += P * V ; l += P * 1 (ones-B mma, no ldsm)
        #pragma unroll
        for (int kk = 0; kk < 4; kk++) {
            unsigned b[8][2];
            #pragma unroll
            for (int p = 0; p < 4; p++)
                ldsm4(b[2*p][0], b[2*p][1], b[2*p+1][0], b[2*p+1][1],
                      Vts + swH(rB[p], kk*16 + eB));
            #pragma unroll
            for (int u = 0; u < 2; u++) {
                const unsigned* a = &pf[u][4*kk];
                #pragma unroll
                for (int nt = 0; nt < 8; nt++) mma16h(o[u][nt], a, b[nt]);
                mma16h(lac[u], a, ones_b);
            }
        }
    }

    // epilogue: normalize (l from the ones-mma C-fragment), write half2 pairs
    int bb = bh >> 4, h = bh & 15;
    #pragma unroll
    for (int u = 0; u < 2; u++) {
        float inv0 = 1.f / lac[u][0], inv1 = 1.f / lac[u][2];
        int q0 = qt*128 + wid*32 + u*16 + g;
        __half* base0 = g_attn + ((size_t)(bb*SEQ + q0) * EMBED) + h*64;
        __half* base1 = base0 + (size_t)8 * EMBED;
        #pragma unroll
        for (int nt = 0; nt < 8; nt++) {
            int d = nt*8 + 2*tg;
            *(__half2*)(base0 + d) = __floats2half2_rn(o[u][nt][0] * inv0, o[u][nt][1] * inv0);
            *(__half2*)(base1 + d) = __floats2half2_rn(o[u][nt][2] * inv1, o[u][nt][3] * inv1);
        }
    }
}

// ============ Kernel 3: output projection (fp32 out, coalesced via bounce) ============
#define OPROJ_STRIDE 132   // floats
__global__ __launch_bounds__(128, 2) void oproj_kernel(float* __restrict__ out)
{
    extern __shared__ __align__(16) __half smem[];
    int row0 = blockIdx.y * 128, col0 = blockIdx.x * 128;
    float acc[4][8][4];
    gemm_core(g_attn, g_wo, row0, col0, smem, acc);

    int tid = threadIdx.x, lane = tid & 31, wid = tid >> 5;
    int g = lane >> 2, tg = lane & 3, wm = wid >> 1, wn = wid & 1;

    __syncthreads();
    float* tile = (float*)smem;   // 128 x OPROJ_STRIDE floats = 67.6KB
    #pragma unroll
    for (int mt = 0; mt < 4; mt++) {
        int r = wm*64 + mt*16 + g;
        #pragma unroll
        for (int nt = 0; nt < 8; nt++) {
            int c = wn*64 + nt*8 + 2*tg;
            *(float2*)(tile + r*OPROJ_STRIDE + c)       = make_float2(acc[mt][nt][0], acc[mt][nt][1]);
            *(float2*)(tile + (r + 8)*OPROJ_STRIDE + c) = make_float2(acc[mt][nt][2], acc[mt][nt][3]);
        }
    }
    __syncthreads();
    #pragma unroll
    for (int i = 0; i < 32; i++) {
        int idx = tid + 128*i;            // 128 r x 32 chunks of float4
        int r = idx >> 5, k4 = (idx & 31) * 4;
        float4 v = *(float4*)(tile + r*OPROJ_STRIDE + k4);
        *(float4*)(out + (size_t)(row0 + r) * EMBED + col0 + k4) = v;
    }
}

// ============ launch ============
extern "C" void kernel_launch(void* const* d_in, const int* in_sizes, int n_in,
                              void* d_out, int out_size)
{
    const float* x  = (const float*)d_in[0];
    const float* Wq = (const float*)d_in[1];
    const float* Wk = (const float*)d_in[2];
    const float* Wv = (const float*)d_in[3];
    const float* Wo = (const float*)d_in[4];
    float* out = (float*)d_out;

    cudaFuncSetAttribute(qkv_kernel,   cudaFuncAttributeMaxDynamicSharedMemorySize, GEMM_SMEM_BYTES);
    cudaFuncSetAttribute(oproj_kernel, cudaFuncAttributeMaxDynamicSharedMemorySize, GEMM_SMEM_BYTES);
    cudaFuncSetAttribute(attn_kernel,  cudaFuncAttributeMaxDynamicSharedMemorySize, ATTN_SMEM_BYTES);

    __half* p_x;  cudaGetSymbolAddress((void**)&p_x,  g_x);
    __half* p_wq; cudaGetSymbolAddress((void**)&p_wq, g_wq);
    __half* p_wk; cudaGetSymbolAddress((void**)&p_wk, g_wk);
    __half* p_wv; cudaGetSymbolAddress((void**)&p_wv, g_wv);
    __half* p_wo; cudaGetSymbolAddress((void**)&p_wo, g_wo);

    int nx8 = MTOK*EMBED/8, nw8 = EMBED*EMBED/8;
    prep_kernel<<<(nx8 + 255)/256, 256>>>(x, p_x, nx8);
    prep_w_kernel<<<dim3(nw8/256, 1, 4), 256>>>(Wq, Wk, Wv, Wo, p_wq, p_wk, p_wv, p_wo);

    qkv_kernel<<<dim3(EMBED/128, MTOK/128, 3), 128, GEMM_SMEM_BYTES>>>();
    attn_kernel<<<dim3(SEQ/128, BATCH*NHEAD), 128, ATTN_SMEM_BYTES>>>();
    oproj_kernel<<<dim3(EMBED/128, MTOK/128), 128, GEMM_SMEM_BYTES>>>(out);
}